// round 12
// baseline (speedup 1.0000x reference)
#include <cuda_runtime.h>
#include <cuda_fp16.h>
#include <cstdint>

#define NN  100000
#define EE  1000000
#define IND 128
#define HID 256
#define GG  64
#define BN_EPS 1e-5f

#define SCAN_B 1024
#define SCAN_NBLK ((NN + SCAN_B - 1) / SCAN_B)   // 98

#define TILE_M 128
#define MBLK ((NN + TILE_M - 1) / TILE_M)        // 782

#define WSCALE 32.0f
#define AINV   0.03125f

// ---------------- scratch (static device globals; no allocation) ----------------
__device__ __half g_feath[(NN + TILE_M) * IND];  // feat * (1/32), fp16, padded
__device__ __half g_aggh[(NN + TILE_M) * IND];   // h_neigh * (1/32), fp16, padded
__device__ int   g_deg[NN];
__device__ int   g_ptr[NN];
__device__ int   g_cur[NN];
__device__ int   g_esrc[EE];
__device__ int   g_bsum[SCAN_NBLK];
__device__ int   g_boff[SCAN_NBLK];
__device__ float g_poolraw[GG * HID];
__device__ int   g_cnt[GG];
__device__ float g_bnstats[8 * HID];
__device__ float g_z1[GG * HID];
__device__ float g_z2[GG * HID];
__device__ float g_p[GG * HID];
__device__ __half g_Whi[256 * 256];              // W * 32 hi
__device__ __half g_Wlo[256 * 256];              // W * 32 lo

// ---------------- helpers ----------------
__device__ __forceinline__ void redF1(float* addr, float v) {
    asm volatile("red.global.add.f32 [%0], %1;" :: "l"(addr), "f"(v) : "memory");
}
__device__ __forceinline__ void redI1(int* addr, int v) {
    asm volatile("red.global.add.s32 [%0], %1;" :: "l"(addr), "r"(v) : "memory");
}
__device__ __forceinline__ uint32_t smem_u32(const void* p) {
    uint32_t a;
    asm("{ .reg .u64 t; cvta.to.shared.u64 t, %1; cvt.u32.u64 %0, t; }"
        : "=r"(a) : "l"(p));
    return a;
}
__device__ __forceinline__ void ldsm4(uint32_t* r, uint32_t a) {
    asm volatile("ldmatrix.sync.aligned.m8n8.x4.shared.b16 {%0,%1,%2,%3}, [%4];"
        : "=r"(r[0]), "=r"(r[1]), "=r"(r[2]), "=r"(r[3]) : "r"(a));
}
__device__ __forceinline__ void ldsm4t(uint32_t* r, uint32_t a) {
    asm volatile("ldmatrix.sync.aligned.m8n8.x4.trans.shared.b16 {%0,%1,%2,%3}, [%4];"
        : "=r"(r[0]), "=r"(r[1]), "=r"(r[2]), "=r"(r[3]) : "r"(a));
}
__device__ __forceinline__ void mma16816(float* d, const uint32_t* a, const uint32_t* b) {
    asm volatile("mma.sync.aligned.m16n8k16.row.col.f32.f16.f16.f32 "
        "{%0,%1,%2,%3}, {%4,%5,%6,%7}, {%8,%9}, {%0,%1,%2,%3};"
        : "+f"(d[0]), "+f"(d[1]), "+f"(d[2]), "+f"(d[3])
        : "r"(a[0]), "r"(a[1]), "r"(a[2]), "r"(a[3]), "r"(b[0]), "r"(b[1]));
}
__device__ __forceinline__ void cpa16(uint32_t d, const void* s) {
    asm volatile("cp.async.cg.shared.global [%0], [%1], 16;" :: "r"(d), "l"(s));
}
__device__ __forceinline__ void cpa8(uint32_t d, const void* s) {
    asm volatile("cp.async.ca.shared.global [%0], [%1], 8;" :: "r"(d), "l"(s));
}
#define CP_COMMIT() asm volatile("cp.async.commit_group;" ::: "memory")
#define CP_WAIT0()  asm volatile("cp.async.wait_group 0;" ::: "memory")

// ---------------- K0: merged init — feat->fp16 image + W prep + zeros ----------
// (NO g_cnt accumulation here: zeroing and accumulation must be separated by a
//  launch boundary; counts are accumulated in scan1_kernel.)
__global__ void init_kernel(const float* __restrict__ feat,
                            const float* __restrict__ W_self,
                            const float* __restrict__ W_neigh) {
    int idx = blockIdx.x * blockDim.x + threadIdx.x;
    // feat conversion: NN*32 uint2 units (the dominant sweep)
    if (idx < NN * (IND / 4)) {
        float4 v = __ldg(((const float4*)feat) + idx);
        __half h0 = __float2half(v.x * AINV);
        __half h1 = __float2half(v.y * AINV);
        __half h2 = __float2half(v.z * AINV);
        __half h3 = __float2half(v.w * AINV);
        uint2 u;
        u.x = ((uint32_t)__half_as_ushort(h1) << 16) | __half_as_ushort(h0);
        u.y = ((uint32_t)__half_as_ushort(h3) << 16) | __half_as_ushort(h2);
        ((uint2*)g_feath)[idx] = u;
    }
    if (idx < 65536) {
        int k = idx >> 8, n = idx & 255;
        float w = ((k < IND) ? W_self[k * HID + n] : W_neigh[(k - IND) * HID + n]) * WSCALE;
        __half hi = __float2half(w);
        __half lo = __float2half(w - __half2float(hi));
        g_Whi[idx] = hi;
        g_Wlo[idx] = lo;
    }
    if (idx < NN) g_deg[idx] = 0;
    if (idx < TILE_M * IND) {                          // zero pad rows
        g_feath[NN * IND + idx] = __ushort_as_half(0);
        g_aggh[NN * IND + idx] = __ushort_as_half(0);
    }
    if (idx < GG * HID) g_poolraw[idx] = 0.f;
    if (idx < GG) g_cnt[idx] = 0;
    if (idx < 6 * HID) g_bnstats[idx] = 0.f;
}

// ---------------- CSR phases ----------------
__global__ void deg_kernel(const int* __restrict__ dst) {
    int e = blockIdx.x * blockDim.x + threadIdx.x;
    if (e < EE) redI1(&g_deg[__ldg(&dst[e])], 1);
}

// scan1 also accumulates per-graph node counts (runs AFTER init zeroed g_cnt)
__global__ __launch_bounds__(SCAN_B) void scan1_kernel(const int* __restrict__ graph_id) {
    __shared__ int sh[SCAN_B];
    __shared__ int cnt[GG];
    int t = threadIdx.x;
    int i = blockIdx.x * SCAN_B + t;
    if (t < GG) cnt[t] = 0;
    sh[t] = (i < NN) ? g_deg[i] : 0;
    __syncthreads();
    if (i < NN) atomicAdd(&cnt[__ldg(&graph_id[i])], 1);
#pragma unroll
    for (int s = SCAN_B / 2; s > 0; s >>= 1) {
        if (t < s) sh[t] += sh[t + s];
        __syncthreads();
    }
    if (t == 0) g_bsum[blockIdx.x] = sh[0];
    if (t < GG && cnt[t]) redI1(&g_cnt[t], cnt[t]);
}

__global__ __launch_bounds__(128) void scan2_kernel() {
    __shared__ int sh[128];
    int t = threadIdx.x;
    int v = (t < SCAN_NBLK) ? g_bsum[t] : 0;
    sh[t] = v;
    __syncthreads();
#pragma unroll
    for (int off = 1; off < 128; off <<= 1) {
        int x = (t >= off) ? sh[t - off] : 0;
        __syncthreads();
        sh[t] += x;
        __syncthreads();
    }
    if (t < SCAN_NBLK) g_boff[t] = sh[t] - v;
}

__global__ __launch_bounds__(SCAN_B) void scan3_kernel() {
    __shared__ int sh[SCAN_B];
    int t = threadIdx.x;
    int i = blockIdx.x * SCAN_B + t;
    int v = (i < NN) ? g_deg[i] : 0;
    sh[t] = v;
    __syncthreads();
#pragma unroll
    for (int off = 1; off < SCAN_B; off <<= 1) {
        int x = (t >= off) ? sh[t - off] : 0;
        __syncthreads();
        sh[t] += x;
        __syncthreads();
    }
    if (i < NN) {
        int pos = g_boff[blockIdx.x] + sh[t] - v;
        g_ptr[i] = pos;
        g_cur[i] = pos;
    }
}

__global__ void fill_kernel(const int* __restrict__ src,
                            const int* __restrict__ dst) {
    int e = blockIdx.x * blockDim.x + threadIdx.x;
    if (e >= EE) return;
    int d = __ldg(&dst[e]);
    int pos = atomicAdd(&g_cur[d], 1);
    g_esrc[pos] = __ldg(&src[e]);
}

// ---------------- K1: gather-aggregate (warp per node, shfl-broadcast indices) ---
__global__ __launch_bounds__(256) void agg_kernel() {
    int t = blockIdx.x * blockDim.x + threadIdx.x;
    int node = t >> 5;
    if (node >= NN) return;
    int lane = t & 31;
    int beg = __ldg(&g_ptr[node]);
    int d = __ldg(&g_deg[node]);
    float2 a0 = make_float2(0.f, 0.f), a1 = make_float2(0.f, 0.f);
    const uint2* base = (const uint2*)g_feath;   // 32 uint2 per row
#pragma unroll 1
    for (int b = 0; b < d; b += 32) {
        int cnt = min(32, d - b);
        int myidx = (b + lane < d) ? __ldg(&g_esrc[beg + b + lane]) : 0;
#pragma unroll 4
        for (int i = 0; i < cnt; i++) {
            int s = __shfl_sync(0xffffffffu, myidx, i);
            uint2 u = __ldg(base + (size_t)s * 32 + lane);
            float2 f0 = __half22float2(*(__half2*)&u.x);
            float2 f1 = __half22float2(*(__half2*)&u.y);
            a0.x += f0.x; a0.y += f0.y; a1.x += f1.x; a1.y += f1.y;
        }
    }
    float sc = 1.f / fmaxf((float)d, 1.f);       // feath already has the 1/32
    __half h0 = __float2half(a0.x * sc);
    __half h1 = __float2half(a0.y * sc);
    __half h2 = __float2half(a1.x * sc);
    __half h3 = __float2half(a1.y * sc);
    uint2 o;
    o.x = ((uint32_t)__half_as_ushort(h1) << 16) | __half_as_ushort(h0);
    o.y = ((uint32_t)__half_as_ushort(h3) << 16) | __half_as_ushort(h2);
    ((uint2*)g_aggh)[(size_t)node * 32 + lane] = o;
}

// ---------------- K2: mma.sync fp16 2-term GEMM, cp.async staged, M=128 N=256 ---
// stage: A [128][80B] @0 (10240), Whi [32][528B] @10240 (16896), Wlo @27136 (16896)
// ST_SZ=44032, double buffered (88064). Epilogue aliases: C half[128][264] @0
// (67584), colsum @67584, colsq @71680, pool @75776 (8192).
#define ST_SZ    44032
#define SOF_WH   10240
#define SOF_WL   27136
#define OFF_CS   67584
#define OFF_CQ   71680
#define OFF_POOL 75776
#define OFF_BSH  88064
#define OFF_GIDS 89088
#define OFF_GRNG 89600
#define DYN_SMEM 89616

__global__ __launch_bounds__(1024, 1) void conv_mma_kernel(
    const float* __restrict__ b_conv, const int* __restrict__ graph_id) {
    extern __shared__ char p0[];
    uint32_t sm = smem_u32(p0);
    float* s_bsh  = (float*)(p0 + OFF_BSH);
    int*   s_gids = (int*)(p0 + OFF_GIDS);
    int*   s_grng = (int*)(p0 + OFF_GRNG);

    int tid = threadIdx.x;
    int wid = tid >> 5;
    int lane = tid & 31;
    int row0 = blockIdx.x * TILE_M;

    if (tid < 256) s_bsh[tid] = b_conv[tid];
    if (tid < TILE_M) {
        int node = row0 + tid;
        s_gids[tid] = (node < NN) ? __ldg(&graph_id[node]) : -1;
    }
    __syncthreads();
    if (tid == 0) {
        int lo = s_gids[0], hi = lo;
#pragma unroll 1
        for (int i = 1; i < TILE_M; i++)
            if (s_gids[i] >= 0) hi = s_gids[i];
        s_grng[0] = lo; s_grng[1] = hi;
    }

    int wm = (wid >> 2) * 16;    // warp M offset (0..112)
    int wn = (wid & 3) * 64;     // warp N offset (0/64/128/192)

    float acc[8][4];
#pragma unroll
    for (int j = 0; j < 8; j++)
#pragma unroll
        for (int d = 0; d < 4; d++) acc[j][d] = 0.f;

    uint32_t Abase = sm + (wm + (lane & 15)) * 80 + (lane >> 4) * 16;
    uint32_t Bbase = sm + SOF_WH + (lane & 15) * 528 + (wn + (lane >> 4) * 8) * 2;

    auto stage = [&](int kc, int buf) {
        uint32_t st = sm + buf * ST_SZ;
        // A: 8B per thread (4 halfs), already fp16 pre-scaled
        {
            int r = tid >> 3, u = tid & 7;
            const __half* srcb = (kc < 4) ? g_feath : g_aggh;
            int kof = (kc & 3) * 32;
            cpa8(st + r * 80 + u * 8,
                 srcb + (size_t)(row0 + r) * IND + kof + u * 4);
        }
        // W hi/lo: 16B per thread each
        {
            int kk = tid >> 5, c = tid & 31;
            size_t so = (size_t)(kc * 32 + kk) * 256 + c * 8;
            cpa16(st + SOF_WH + kk * 528 + c * 16, g_Whi + so);
            cpa16(st + SOF_WL + kk * 528 + c * 16, g_Wlo + so);
        }
    };
    auto compute = [&](int buf) {
        uint32_t so = buf * ST_SZ;
#pragma unroll
        for (int ks = 0; ks < 2; ks++) {
            uint32_t ab = Abase + so + ks * 32;
            uint32_t bb = Bbase + so + ks * 8448;   // ks*16*528
            uint32_t ah[4], f[4];
            ldsm4(ah, ab);
#pragma unroll
            for (int c = 0; c < 4; c++) {
                ldsm4t(f, bb + c * 32);
                mma16816(acc[2 * c], ah, f);
                mma16816(acc[2 * c + 1], ah, f + 2);
                ldsm4t(f, bb + 16896 + c * 32);
                mma16816(acc[2 * c], ah, f);
                mma16816(acc[2 * c + 1], ah, f + 2);
            }
        }
    };

    // -------- main loop: 8 K-chunks of 32, double-buffered cp.async --------
    stage(0, 0);
    CP_COMMIT();
    CP_WAIT0();
    __syncthreads();
#pragma unroll 1
    for (int kc = 0; kc < 8; kc++) {
        if (kc < 7) { stage(kc + 1, (kc + 1) & 1); CP_COMMIT(); }
        compute(kc & 1);
        if (kc < 7) CP_WAIT0();
        __syncthreads();
    }

    // -------- epilogue --------
    __half* C  = (__half*)p0;                 // [128][264]
    float* s_cs = (float*)(p0 + OFF_CS);      // [4][256]
    float* s_cq = (float*)(p0 + OFF_CQ);      // [4][256]
    float* s_pl = (float*)(p0 + OFF_POOL);    // [8][256]
#pragma unroll
    for (int j = 0; j < 8; j++) {
        int r0 = wm + (lane >> 2);
        int c = wn + j * 8 + (lane & 3) * 2;
        __half2 lo2 = __floats2half2_rn(acc[j][0], acc[j][1]);
        __half2 hi2 = __floats2half2_rn(acc[j][2], acc[j][3]);
        *(__half2*)&C[r0 * 264 + c] = lo2;
        *(__half2*)&C[(r0 + 8) * 264 + c] = hi2;
    }
    __syncthreads();
    // zero pool slots
    ((float*)s_pl)[tid] = 0.f;
    ((float*)s_pl)[tid + 1024] = 0.f;
    __syncthreads();

    int col = tid & 255, q = tid >> 8;        // quarter of rows (32 each)
    int glo = s_grng[0], ghi = s_grng[1];
    {
        float b = s_bsh[col];
        float sum = 0.f, sq = 0.f;
        int curg = -1;
        float run = 0.f;
#pragma unroll 4
        for (int rr = q * 32; rr < q * 32 + 32; rr++) {
            int gd = s_gids[rr];
            float v = __half2float(C[rr * 264 + col]) + b;
            v = (gd >= 0) ? fmaxf(v, 0.f) : 0.f;
            C[rr * 264 + col] = __float2half(v);
            sum += v; sq += v * v;
            if (gd != curg) {
                int slot = curg - glo;
                if (curg >= 0 && slot < 8) atomicAdd(&s_pl[slot * 256 + col], run);
                run = 0.f; curg = gd;
            }
            run += v;
        }
        int slot = curg - glo;
        if (curg >= 0 && slot < 8) atomicAdd(&s_pl[slot * 256 + col], run);
        s_cs[q * 256 + col] = sum;
        s_cq[q * 256 + col] = sq;
    }
    __syncthreads();
    if (tid < 256) {
        float s = s_cs[col] + s_cs[256 + col] + s_cs[512 + col] + s_cs[768 + col];
        redF1(&g_bnstats[col], s);
#pragma unroll 1
        for (int t = 0; t < 8; t++) {
            int g = glo + t;
            if (g <= ghi) redF1(&g_poolraw[g * HID + col], s_pl[t * 256 + col]);
        }
    } else if (tid < 512) {
        int c2 = tid - 256;
        float s = s_cq[c2] + s_cq[256 + c2] + s_cq[512 + c2] + s_cq[768 + c2];
        redF1(&g_bnstats[256 + c2], s);
    }
    // rare: block spans more than 8 graphs
#pragma unroll 1
    for (int p = 1; glo + 8 * p <= ghi; p++) {
        __syncthreads();
        ((float*)s_pl)[tid] = 0.f;
        ((float*)s_pl)[tid + 1024] = 0.f;
        __syncthreads();
        int base = glo + 8 * p;
        int curg = -1;
        float run = 0.f;
#pragma unroll 1
        for (int rr = q * 32; rr < q * 32 + 32; rr++) {
            int gd = s_gids[rr];
            float v = __half2float(C[rr * 264 + col]);
            if (gd != curg) {
                int slot = curg - base;
                if (slot >= 0 && slot < 8) atomicAdd(&s_pl[slot * 256 + col], run);
                run = 0.f; curg = gd;
            }
            run += v;
        }
        int slot = curg - base;
        if (slot >= 0 && slot < 8) atomicAdd(&s_pl[slot * 256 + col], run);
        __syncthreads();
        if (tid < 256) {
#pragma unroll 1
            for (int t = 0; t < 8; t++) {
                int g = base + t;
                if (g <= ghi) redF1(&g_poolraw[g * HID + col], s_pl[t * 256 + col]);
            }
        }
    }
}

// ---------------- K4: z1 = relu(pooled @ W_lp + b) + stats (BN fold inline) -------
__global__ __launch_bounds__(HID) void lp1_kernel(const float* __restrict__ W_lp,
                                                  const float* __restrict__ b_lp,
                                                  const float* __restrict__ gamma,
                                                  const float* __restrict__ beta) {
    __shared__ float row[HID];
    int g = blockIdx.x, c = threadIdx.x;
    float mean = g_bnstats[c] * (1.0f / NN);
    float var  = g_bnstats[256 + c] * (1.0f / NN) - mean * mean;
    float sc = gamma[c] * rsqrtf(var + BN_EPS);
    float sh = beta[c] - mean * sc;
    float cntf = (float)g_cnt[g];
    row[c] = fmaf(g_poolraw[g * HID + c], sc, cntf * sh);
    __syncthreads();
    float acc = b_lp[c];
#pragma unroll 8
    for (int k = 0; k < HID; k++) acc = fmaf(row[k], __ldg(&W_lp[k * HID + c]), acc);
    float r = fmaxf(acc, 0.f);
    g_z1[g * HID + c] = r;
    atomicAdd(&g_bnstats[512 + c], r);
    atomicAdd(&g_bnstats[768 + c], r * r);
}

// ---------------- K5: BN(z1) -> p, z2 = relu(p @ W_lp + b) + stats ----------------
__global__ __launch_bounds__(HID) void lp2_kernel(const float* __restrict__ W_lp,
                                                  const float* __restrict__ b_lp,
                                                  const float* __restrict__ gamma,
                                                  const float* __restrict__ beta,
                                                  float* __restrict__ out_p) {
    __shared__ float row[HID];
    int g = blockIdx.x, c = threadIdx.x;
    float r = g_z1[g * HID + c];
    float mean = g_bnstats[512 + c] * (1.f / GG);
    float var  = g_bnstats[768 + c] * (1.f / GG) - mean * mean;
    float p = (r - mean) * rsqrtf(var + BN_EPS) * gamma[c] + beta[c];
    out_p[g * HID + c] = p;
    row[c] = p;
    __syncthreads();
    float acc = b_lp[c];
#pragma unroll 8
    for (int k = 0; k < HID; k++) acc = fmaf(row[k], __ldg(&W_lp[k * HID + c]), acc);
    float r2 = fmaxf(acc, 0.f);
    g_z2[g * HID + c] = r2;
    atomicAdd(&g_bnstats[1024 + c], r2);
    atomicAdd(&g_bnstats[1280 + c], r2 * r2);
}

// ---------------- K6: BN(z2) + log_softmax ----------------
__global__ __launch_bounds__(HID) void lp3_kernel(const float* __restrict__ gamma,
                                                  const float* __restrict__ beta,
                                                  float* __restrict__ out) {
    __shared__ float buf[HID];
    int g = blockIdx.x, c = threadIdx.x;
    float r = g_z2[g * HID + c];
    float mean = g_bnstats[1024 + c] * (1.f / GG);
    float var  = g_bnstats[1280 + c] * (1.f / GG) - mean * mean;
    float o = (r - mean) * rsqrtf(var + BN_EPS) * gamma[c] + beta[c];
    buf[c] = o;
    __syncthreads();
    for (int s = 128; s > 0; s >>= 1) {
        if (c < s) buf[c] = fmaxf(buf[c], buf[c + s]);
        __syncthreads();
    }
    float m = buf[0];
    __syncthreads();
    float e = expf(o - m);
    buf[c] = e;
    __syncthreads();
    for (int s = 128; s > 0; s >>= 1) {
        if (c < s) buf[c] += buf[c + s];
        __syncthreads();
    }
    float lse = logf(buf[0]);
    out[g * HID + c] = o - m - lse;
}

// ---------------- launch ----------------
extern "C" void kernel_launch(void* const* d_in, const int* in_sizes, int n_in,
                              void* d_out, int out_size) {
    const float* feat       = (const float*)d_in[0];
    const float* W_self     = (const float*)d_in[1];
    const float* W_neigh    = (const float*)d_in[2];
    const float* b_conv     = (const float*)d_in[3];
    const float* gamma_conv = (const float*)d_in[4];
    const float* beta_conv  = (const float*)d_in[5];
    const float* W_lp       = (const float*)d_in[6];
    const float* b_lp       = (const float*)d_in[7];
    const float* gamma_lp   = (const float*)d_in[8];
    const float* beta_lp    = (const float*)d_in[9];
    const int*   src        = (const int*)d_in[10];
    const int*   dst        = (const int*)d_in[11];
    const int*   graph_id   = (const int*)d_in[12];
    float* out = (float*)d_out;

    float* out_p;
    if (out_size >= 2 * GG * HID) {
        out_p = out + GG * HID;
    } else {
        void* pp = nullptr;
        cudaGetSymbolAddress(&pp, g_p);
        out_p = (float*)pp;
    }

    cudaFuncSetAttribute(conv_mma_kernel,
                         cudaFuncAttributeMaxDynamicSharedMemorySize, DYN_SMEM);

    init_kernel<<<(NN * (IND / 4) + 255) / 256, 256>>>(feat, W_self, W_neigh);
    deg_kernel<<<(EE + 255) / 256, 256>>>(dst);
    scan1_kernel<<<SCAN_NBLK, SCAN_B>>>(graph_id);
    scan2_kernel<<<1, 128>>>();
    scan3_kernel<<<SCAN_NBLK, SCAN_B>>>();
    fill_kernel<<<(EE + 255) / 256, 256>>>(src, dst);
    agg_kernel<<<(NN * 32 + 255) / 256, 256>>>();
    conv_mma_kernel<<<MBLK, 1024, DYN_SMEM>>>(b_conv, graph_id);
    lp1_kernel<<<GG, HID>>>(W_lp, b_lp, gamma_conv, beta_conv);
    lp2_kernel<<<GG, HID>>>(W_lp, b_lp, gamma_lp, beta_lp, out_p);
    lp3_kernel<<<GG, HID>>>(gamma_lp, beta_lp, out);
}

// round 13
// speedup vs baseline: 1.2582x; 1.2582x over previous
#include <cuda_runtime.h>
#include <cuda_fp16.h>
#include <cstdint>

#define NN  100000
#define EE  1000000
#define IND 128
#define HID 256
#define GG  64
#define BN_EPS 1e-5f

#define SCAN_B 1024
#define SCAN_NBLK ((NN + SCAN_B - 1) / SCAN_B)   // 98

#define TILE_M 128
#define MBLK ((NN + TILE_M - 1) / TILE_M)        // 782

#define WSCALE 32.0f
#define AINV   0.03125f

// ---------------- scratch (static device globals; no allocation) ----------------
__device__ __half g_feath[(NN + TILE_M) * IND];  // feat * (1/32), fp16, padded
__device__ __half g_aggh[(NN + TILE_M) * IND];   // h_neigh * (1/32), fp16, padded
__device__ int   g_deg[NN];
__device__ int   g_ptr[NN];
__device__ int   g_cur[NN];
__device__ int   g_esrc[EE];
__device__ int   g_bsum[SCAN_NBLK];
__device__ int   g_boff[SCAN_NBLK];
__device__ float g_poolraw[GG * HID];
__device__ int   g_cnt[GG];
__device__ float g_bnstats[8 * HID];
__device__ float g_z1[GG * HID];
__device__ float g_z2[GG * HID];
__device__ float g_p[GG * HID];
__device__ __half g_Whi[256 * 256];              // W * 32 hi
__device__ __half g_Wlo[256 * 256];              // W * 32 lo

// ---------------- helpers ----------------
__device__ __forceinline__ void redF1(float* addr, float v) {
    asm volatile("red.global.add.f32 [%0], %1;" :: "l"(addr), "f"(v) : "memory");
}
__device__ __forceinline__ void redI1(int* addr, int v) {
    asm volatile("red.global.add.s32 [%0], %1;" :: "l"(addr), "r"(v) : "memory");
}
__device__ __forceinline__ uint32_t smem_u32(const void* p) {
    uint32_t a;
    asm("{ .reg .u64 t; cvta.to.shared.u64 t, %1; cvt.u32.u64 %0, t; }"
        : "=r"(a) : "l"(p));
    return a;
}
__device__ __forceinline__ void ldsm4(uint32_t* r, uint32_t a) {
    asm volatile("ldmatrix.sync.aligned.m8n8.x4.shared.b16 {%0,%1,%2,%3}, [%4];"
        : "=r"(r[0]), "=r"(r[1]), "=r"(r[2]), "=r"(r[3]) : "r"(a));
}
__device__ __forceinline__ void ldsm4t(uint32_t* r, uint32_t a) {
    asm volatile("ldmatrix.sync.aligned.m8n8.x4.trans.shared.b16 {%0,%1,%2,%3}, [%4];"
        : "=r"(r[0]), "=r"(r[1]), "=r"(r[2]), "=r"(r[3]) : "r"(a));
}
__device__ __forceinline__ void mma16816(float* d, const uint32_t* a, const uint32_t* b) {
    asm volatile("mma.sync.aligned.m16n8k16.row.col.f32.f16.f16.f32 "
        "{%0,%1,%2,%3}, {%4,%5,%6,%7}, {%8,%9}, {%0,%1,%2,%3};"
        : "+f"(d[0]), "+f"(d[1]), "+f"(d[2]), "+f"(d[3])
        : "r"(a[0]), "r"(a[1]), "r"(a[2]), "r"(a[3]), "r"(b[0]), "r"(b[1]));
}
__device__ __forceinline__ void cpa16(uint32_t d, const void* s) {
    asm volatile("cp.async.cg.shared.global [%0], [%1], 16;" :: "r"(d), "l"(s));
}
__device__ __forceinline__ void cpa8(uint32_t d, const void* s) {
    asm volatile("cp.async.ca.shared.global [%0], [%1], 8;" :: "r"(d), "l"(s));
}
#define CP_COMMIT() asm volatile("cp.async.commit_group;" ::: "memory")
#define CP_WAIT0()  asm volatile("cp.async.wait_group 0;" ::: "memory")

// ---------------- K0: merged init — feat->fp16 image + W prep + zeros ----------
// (g_cnt accumulation happens in scan1_kernel, after this launch's zeroing.)
__global__ void init_kernel(const float* __restrict__ feat,
                            const float* __restrict__ W_self,
                            const float* __restrict__ W_neigh) {
    int idx = blockIdx.x * blockDim.x + threadIdx.x;
    // feat conversion: NN*32 uint2 units (the dominant sweep)
    if (idx < NN * (IND / 4)) {
        float4 v = __ldg(((const float4*)feat) + idx);
        __half h0 = __float2half(v.x * AINV);
        __half h1 = __float2half(v.y * AINV);
        __half h2 = __float2half(v.z * AINV);
        __half h3 = __float2half(v.w * AINV);
        uint2 u;
        u.x = ((uint32_t)__half_as_ushort(h1) << 16) | __half_as_ushort(h0);
        u.y = ((uint32_t)__half_as_ushort(h3) << 16) | __half_as_ushort(h2);
        ((uint2*)g_feath)[idx] = u;
    }
    if (idx < 65536) {
        int k = idx >> 8, n = idx & 255;
        float w = ((k < IND) ? W_self[k * HID + n] : W_neigh[(k - IND) * HID + n]) * WSCALE;
        __half hi = __float2half(w);
        __half lo = __float2half(w - __half2float(hi));
        g_Whi[idx] = hi;
        g_Wlo[idx] = lo;
    }
    if (idx < NN) g_deg[idx] = 0;
    if (idx < TILE_M * IND) {                          // zero pad rows
        g_feath[NN * IND + idx] = __ushort_as_half(0);
        g_aggh[NN * IND + idx] = __ushort_as_half(0);
    }
    if (idx < GG * HID) g_poolraw[idx] = 0.f;
    if (idx < GG) g_cnt[idx] = 0;
    if (idx < 6 * HID) g_bnstats[idx] = 0.f;
}

// ---------------- CSR phases ----------------
__global__ void deg_kernel(const int* __restrict__ dst) {
    int e = blockIdx.x * blockDim.x + threadIdx.x;
    if (e < EE) redI1(&g_deg[__ldg(&dst[e])], 1);
}

// scan1 also accumulates per-graph node counts (runs AFTER init zeroed g_cnt)
__global__ __launch_bounds__(SCAN_B) void scan1_kernel(const int* __restrict__ graph_id) {
    __shared__ int sh[SCAN_B];
    __shared__ int cnt[GG];
    int t = threadIdx.x;
    int i = blockIdx.x * SCAN_B + t;
    if (t < GG) cnt[t] = 0;
    sh[t] = (i < NN) ? g_deg[i] : 0;
    __syncthreads();
    if (i < NN) atomicAdd(&cnt[__ldg(&graph_id[i])], 1);
#pragma unroll
    for (int s = SCAN_B / 2; s > 0; s >>= 1) {
        if (t < s) sh[t] += sh[t + s];
        __syncthreads();
    }
    if (t == 0) g_bsum[blockIdx.x] = sh[0];
    if (t < GG && cnt[t]) redI1(&g_cnt[t], cnt[t]);
}

__global__ __launch_bounds__(128) void scan2_kernel() {
    __shared__ int sh[128];
    int t = threadIdx.x;
    int v = (t < SCAN_NBLK) ? g_bsum[t] : 0;
    sh[t] = v;
    __syncthreads();
#pragma unroll
    for (int off = 1; off < 128; off <<= 1) {
        int x = (t >= off) ? sh[t - off] : 0;
        __syncthreads();
        sh[t] += x;
        __syncthreads();
    }
    if (t < SCAN_NBLK) g_boff[t] = sh[t] - v;
}

__global__ __launch_bounds__(SCAN_B) void scan3_kernel() {
    __shared__ int sh[SCAN_B];
    int t = threadIdx.x;
    int i = blockIdx.x * SCAN_B + t;
    int v = (i < NN) ? g_deg[i] : 0;
    sh[t] = v;
    __syncthreads();
#pragma unroll
    for (int off = 1; off < SCAN_B; off <<= 1) {
        int x = (t >= off) ? sh[t - off] : 0;
        __syncthreads();
        sh[t] += x;
        __syncthreads();
    }
    if (i < NN) {
        int pos = g_boff[blockIdx.x] + sh[t] - v;
        g_ptr[i] = pos;
        g_cur[i] = pos;
    }
}

__global__ void fill_kernel(const int* __restrict__ src,
                            const int* __restrict__ dst) {
    int e = blockIdx.x * blockDim.x + threadIdx.x;
    if (e >= EE) return;
    int d = __ldg(&dst[e]);
    int pos = atomicAdd(&g_cur[d], 1);
    g_esrc[pos] = __ldg(&src[e]);
}

// ---------------- K1: gather-aggregate (warp per node, uniform esrc load) -------
// (R10 form — measured fastest; shfl-broadcast variant regressed in R12.)
__global__ __launch_bounds__(256) void agg_kernel() {
    int t = blockIdx.x * blockDim.x + threadIdx.x;
    int node = t >> 5;
    if (node >= NN) return;
    int lane = t & 31;
    int beg = __ldg(&g_ptr[node]);
    int d = __ldg(&g_deg[node]);
    float2 a0 = make_float2(0.f, 0.f), a1 = make_float2(0.f, 0.f);
    const uint2* base = (const uint2*)g_feath;   // 32 uint2 per row
    for (int i = 0; i < d; i++) {
        int s = __ldg(&g_esrc[beg + i]);
        uint2 u = __ldg(base + (size_t)s * 32 + lane);
        float2 f0 = __half22float2(*(__half2*)&u.x);
        float2 f1 = __half22float2(*(__half2*)&u.y);
        a0.x += f0.x; a0.y += f0.y; a1.x += f1.x; a1.y += f1.y;
    }
    float sc = 1.f / fmaxf((float)d, 1.f);       // feath already has the 1/32
    __half h0 = __float2half(a0.x * sc);
    __half h1 = __float2half(a0.y * sc);
    __half h2 = __float2half(a1.x * sc);
    __half h3 = __float2half(a1.y * sc);
    uint2 o;
    o.x = ((uint32_t)__half_as_ushort(h1) << 16) | __half_as_ushort(h0);
    o.y = ((uint32_t)__half_as_ushort(h3) << 16) | __half_as_ushort(h2);
    ((uint2*)g_aggh)[(size_t)node * 32 + lane] = o;
}

// ---------------- K2: mma.sync fp16 2-term GEMM, cp.async staged, M=128 N=256 ---
// stage: A [128][80B] @0 (10240), Whi [32][528B] @10240 (16896), Wlo @27136 (16896)
// ST_SZ=44032, double buffered (88064). Epilogue aliases: C half[128][264] @0
// (67584), colsum @67584, colsq @71680, pool @75776 (8192).
#define ST_SZ    44032
#define SOF_WH   10240
#define SOF_WL   27136
#define OFF_CS   67584
#define OFF_CQ   71680
#define OFF_POOL 75776
#define OFF_BSH  88064
#define OFF_GIDS 89088
#define OFF_GRNG 89600
#define DYN_SMEM 89616

__global__ __launch_bounds__(1024, 1) void conv_mma_kernel(
    const float* __restrict__ b_conv, const int* __restrict__ graph_id) {
    extern __shared__ char p0[];
    uint32_t sm = smem_u32(p0);
    float* s_bsh  = (float*)(p0 + OFF_BSH);
    int*   s_gids = (int*)(p0 + OFF_GIDS);
    int*   s_grng = (int*)(p0 + OFF_GRNG);

    int tid = threadIdx.x;
    int wid = tid >> 5;
    int lane = tid & 31;
    int row0 = blockIdx.x * TILE_M;

    if (tid < 256) s_bsh[tid] = b_conv[tid];
    if (tid < TILE_M) {
        int node = row0 + tid;
        s_gids[tid] = (node < NN) ? __ldg(&graph_id[node]) : -1;
    }
    __syncthreads();
    if (tid == 0) {
        int lo = s_gids[0], hi = lo;
#pragma unroll 1
        for (int i = 1; i < TILE_M; i++)
            if (s_gids[i] >= 0) hi = s_gids[i];
        s_grng[0] = lo; s_grng[1] = hi;
    }

    int wm = (wid >> 2) * 16;    // warp M offset (0..112)
    int wn = (wid & 3) * 64;     // warp N offset (0/64/128/192)

    float acc[8][4];
#pragma unroll
    for (int j = 0; j < 8; j++)
#pragma unroll
        for (int d = 0; d < 4; d++) acc[j][d] = 0.f;

    uint32_t Abase = sm + (wm + (lane & 15)) * 80 + (lane >> 4) * 16;
    uint32_t Bbase = sm + SOF_WH + (lane & 15) * 528 + (wn + (lane >> 4) * 8) * 2;

    auto stage = [&](int kc, int buf) {
        uint32_t st = sm + buf * ST_SZ;
        // A: 8B per thread (4 halfs), already fp16 pre-scaled
        {
            int r = tid >> 3, u = tid & 7;
            const __half* srcb = (kc < 4) ? g_feath : g_aggh;
            int kof = (kc & 3) * 32;
            cpa8(st + r * 80 + u * 8,
                 srcb + (size_t)(row0 + r) * IND + kof + u * 4);
        }
        // W hi/lo: 16B per thread each
        {
            int kk = tid >> 5, c = tid & 31;
            size_t so = (size_t)(kc * 32 + kk) * 256 + c * 8;
            cpa16(st + SOF_WH + kk * 528 + c * 16, g_Whi + so);
            cpa16(st + SOF_WL + kk * 528 + c * 16, g_Wlo + so);
        }
    };
    auto compute = [&](int buf) {
        uint32_t so = buf * ST_SZ;
#pragma unroll
        for (int ks = 0; ks < 2; ks++) {
            uint32_t ab = Abase + so + ks * 32;
            uint32_t bb = Bbase + so + ks * 8448;   // ks*16*528
            uint32_t ah[4], f[4];
            ldsm4(ah, ab);
#pragma unroll
            for (int c = 0; c < 4; c++) {
                ldsm4t(f, bb + c * 32);
                mma16816(acc[2 * c], ah, f);
                mma16816(acc[2 * c + 1], ah, f + 2);
                ldsm4t(f, bb + 16896 + c * 32);
                mma16816(acc[2 * c], ah, f);
                mma16816(acc[2 * c + 1], ah, f + 2);
            }
        }
    };

    // -------- main loop: 8 K-chunks of 32, double-buffered cp.async --------
    stage(0, 0);
    CP_COMMIT();
    CP_WAIT0();
    __syncthreads();
#pragma unroll 1
    for (int kc = 0; kc < 8; kc++) {
        if (kc < 7) { stage(kc + 1, (kc + 1) & 1); CP_COMMIT(); }
        compute(kc & 1);
        if (kc < 7) CP_WAIT0();
        __syncthreads();
    }

    // -------- epilogue --------
    __half* C  = (__half*)p0;                 // [128][264]
    float* s_cs = (float*)(p0 + OFF_CS);      // [4][256]
    float* s_cq = (float*)(p0 + OFF_CQ);      // [4][256]
    float* s_pl = (float*)(p0 + OFF_POOL);    // [8][256]
#pragma unroll
    for (int j = 0; j < 8; j++) {
        int r0 = wm + (lane >> 2);
        int c = wn + j * 8 + (lane & 3) * 2;
        __half2 lo2 = __floats2half2_rn(acc[j][0], acc[j][1]);
        __half2 hi2 = __floats2half2_rn(acc[j][2], acc[j][3]);
        *(__half2*)&C[r0 * 264 + c] = lo2;
        *(__half2*)&C[(r0 + 8) * 264 + c] = hi2;
    }
    __syncthreads();
    // zero pool slots
    ((float*)s_pl)[tid] = 0.f;
    ((float*)s_pl)[tid + 1024] = 0.f;
    __syncthreads();

    int col = tid & 255, q = tid >> 8;        // quarter of rows (32 each)
    int glo = s_grng[0], ghi = s_grng[1];
    {
        float b = s_bsh[col];
        float sum = 0.f, sq = 0.f;
        int curg = -1;
        float run = 0.f;
#pragma unroll 4
        for (int rr = q * 32; rr < q * 32 + 32; rr++) {
            int gd = s_gids[rr];
            float v = __half2float(C[rr * 264 + col]) + b;
            v = (gd >= 0) ? fmaxf(v, 0.f) : 0.f;
            C[rr * 264 + col] = __float2half(v);
            sum += v; sq += v * v;
            if (gd != curg) {
                int slot = curg - glo;
                if (curg >= 0 && slot < 8) atomicAdd(&s_pl[slot * 256 + col], run);
                run = 0.f; curg = gd;
            }
            run += v;
        }
        int slot = curg - glo;
        if (curg >= 0 && slot < 8) atomicAdd(&s_pl[slot * 256 + col], run);
        s_cs[q * 256 + col] = sum;
        s_cq[q * 256 + col] = sq;
    }
    __syncthreads();
    if (tid < 256) {
        float s = s_cs[col] + s_cs[256 + col] + s_cs[512 + col] + s_cs[768 + col];
        redF1(&g_bnstats[col], s);
#pragma unroll 1
        for (int t = 0; t < 8; t++) {
            int g = glo + t;
            if (g <= ghi) redF1(&g_poolraw[g * HID + col], s_pl[t * 256 + col]);
        }
    } else if (tid < 512) {
        int c2 = tid - 256;
        float s = s_cq[c2] + s_cq[256 + c2] + s_cq[512 + c2] + s_cq[768 + c2];
        redF1(&g_bnstats[256 + c2], s);
    }
    // rare: block spans more than 8 graphs
#pragma unroll 1
    for (int p = 1; glo + 8 * p <= ghi; p++) {
        __syncthreads();
        ((float*)s_pl)[tid] = 0.f;
        ((float*)s_pl)[tid + 1024] = 0.f;
        __syncthreads();
        int base = glo + 8 * p;
        int curg = -1;
        float run = 0.f;
#pragma unroll 1
        for (int rr = q * 32; rr < q * 32 + 32; rr++) {
            int gd = s_gids[rr];
            float v = __half2float(C[rr * 264 + col]);
            if (gd != curg) {
                int slot = curg - base;
                if (slot >= 0 && slot < 8) atomicAdd(&s_pl[slot * 256 + col], run);
                run = 0.f; curg = gd;
            }
            run += v;
        }
        int slot = curg - base;
        if (slot >= 0 && slot < 8) atomicAdd(&s_pl[slot * 256 + col], run);
        __syncthreads();
        if (tid < 256) {
#pragma unroll 1
            for (int t = 0; t < 8; t++) {
                int g = base + t;
                if (g <= ghi) redF1(&g_poolraw[g * HID + col], s_pl[t * 256 + col]);
            }
        }
    }
}

// ---------------- K4: z1 = relu(pooled @ W_lp + b) + stats (BN fold inline) -------
__global__ __launch_bounds__(HID) void lp1_kernel(const float* __restrict__ W_lp,
                                                  const float* __restrict__ b_lp,
                                                  const float* __restrict__ gamma,
                                                  const float* __restrict__ beta) {
    __shared__ float row[HID];
    int g = blockIdx.x, c = threadIdx.x;
    float mean = g_bnstats[c] * (1.0f / NN);
    float var  = g_bnstats[256 + c] * (1.0f / NN) - mean * mean;
    float sc = gamma[c] * rsqrtf(var + BN_EPS);
    float sh = beta[c] - mean * sc;
    float cntf = (float)g_cnt[g];
    row[c] = fmaf(g_poolraw[g * HID + c], sc, cntf * sh);
    __syncthreads();
    float acc = b_lp[c];
#pragma unroll 8
    for (int k = 0; k < HID; k++) acc = fmaf(row[k], __ldg(&W_lp[k * HID + c]), acc);
    float r = fmaxf(acc, 0.f);
    g_z1[g * HID + c] = r;
    atomicAdd(&g_bnstats[512 + c], r);
    atomicAdd(&g_bnstats[768 + c], r * r);
}

// ---------------- K5: BN(z1) -> p, z2 = relu(p @ W_lp + b) + stats ----------------
__global__ __launch_bounds__(HID) void lp2_kernel(const float* __restrict__ W_lp,
                                                  const float* __restrict__ b_lp,
                                                  const float* __restrict__ gamma,
                                                  const float* __restrict__ beta,
                                                  float* __restrict__ out_p) {
    __shared__ float row[HID];
    int g = blockIdx.x, c = threadIdx.x;
    float r = g_z1[g * HID + c];
    float mean = g_bnstats[512 + c] * (1.f / GG);
    float var  = g_bnstats[768 + c] * (1.f / GG) - mean * mean;
    float p = (r - mean) * rsqrtf(var + BN_EPS) * gamma[c] + beta[c];
    out_p[g * HID + c] = p;
    row[c] = p;
    __syncthreads();
    float acc = b_lp[c];
#pragma unroll 8
    for (int k = 0; k < HID; k++) acc = fmaf(row[k], __ldg(&W_lp[k * HID + c]), acc);
    float r2 = fmaxf(acc, 0.f);
    g_z2[g * HID + c] = r2;
    atomicAdd(&g_bnstats[1024 + c], r2);
    atomicAdd(&g_bnstats[1280 + c], r2 * r2);
}

// ---------------- K6: BN(z2) + log_softmax ----------------
__global__ __launch_bounds__(HID) void lp3_kernel(const float* __restrict__ gamma,
                                                  const float* __restrict__ beta,
                                                  float* __restrict__ out) {
    __shared__ float buf[HID];
    int g = blockIdx.x, c = threadIdx.x;
    float r = g_z2[g * HID + c];
    float mean = g_bnstats[1024 + c] * (1.f / GG);
    float var  = g_bnstats[1280 + c] * (1.f / GG) - mean * mean;
    float o = (r - mean) * rsqrtf(var + BN_EPS) * gamma[c] + beta[c];
    buf[c] = o;
    __syncthreads();
    for (int s = 128; s > 0; s >>= 1) {
        if (c < s) buf[c] = fmaxf(buf[c], buf[c + s]);
        __syncthreads();
    }
    float m = buf[0];
    __syncthreads();
    float e = expf(o - m);
    buf[c] = e;
    __syncthreads();
    for (int s = 128; s > 0; s >>= 1) {
        if (c < s) buf[c] += buf[c + s];
        __syncthreads();
    }
    float lse = logf(buf[0]);
    out[g * HID + c] = o - m - lse;
}

// ---------------- launch ----------------
extern "C" void kernel_launch(void* const* d_in, const int* in_sizes, int n_in,
                              void* d_out, int out_size) {
    const float* feat       = (const float*)d_in[0];
    const float* W_self     = (const float*)d_in[1];
    const float* W_neigh    = (const float*)d_in[2];
    const float* b_conv     = (const float*)d_in[3];
    const float* gamma_conv = (const float*)d_in[4];
    const float* beta_conv  = (const float*)d_in[5];
    const float* W_lp       = (const float*)d_in[6];
    const float* b_lp       = (const float*)d_in[7];
    const float* gamma_lp   = (const float*)d_in[8];
    const float* beta_lp    = (const float*)d_in[9];
    const int*   src        = (const int*)d_in[10];
    const int*   dst        = (const int*)d_in[11];
    const int*   graph_id   = (const int*)d_in[12];
    float* out = (float*)d_out;

    float* out_p;
    if (out_size >= 2 * GG * HID) {
        out_p = out + GG * HID;
    } else {
        void* pp = nullptr;
        cudaGetSymbolAddress(&pp, g_p);
        out_p = (float*)pp;
    }

    cudaFuncSetAttribute(conv_mma_kernel,
                         cudaFuncAttributeMaxDynamicSharedMemorySize, DYN_SMEM);

    init_kernel<<<(NN * (IND / 4) + 255) / 256, 256>>>(feat, W_self, W_neigh);
    deg_kernel<<<(EE + 255) / 256, 256>>>(dst);
    scan1_kernel<<<SCAN_NBLK, SCAN_B>>>(graph_id);
    scan2_kernel<<<1, 128>>>();
    scan3_kernel<<<SCAN_NBLK, SCAN_B>>>();
    fill_kernel<<<(EE + 255) / 256, 256>>>(src, dst);
    agg_kernel<<<(NN * 32 + 255) / 256, 256>>>();
    conv_mma_kernel<<<MBLK, 1024, DYN_SMEM>>>(b_conv, graph_id);
    lp1_kernel<<<GG, HID>>>(W_lp, b_lp, gamma_conv, beta_conv);
    lp2_kernel<<<GG, HID>>>(W_lp, b_lp, gamma_lp, beta_lp, out_p);
    lp3_kernel<<<GG, HID>>>(gamma_lp, beta_lp, out);
}

// round 14
// speedup vs baseline: 1.4461x; 1.1493x over previous
#include <cuda_runtime.h>
#include <cuda_fp16.h>
#include <cstdint>

#define NN  100000
#define EE  1000000
#define IND 128
#define HID 256
#define GG  64
#define BN_EPS 1e-5f

#define SCAN_B 1024
#define SCAN_NBLK ((NN + SCAN_B - 1) / SCAN_B)   // 98

#define TILE_M 128
#define MBLK ((NN + TILE_M - 1) / TILE_M)        // 782

#define WSCALE 32.0f
#define AINV   0.03125f

// ---------------- scratch (static device globals; no allocation) ----------------
__device__ __half g_feath[(NN + TILE_M) * IND];  // feat * (1/32), fp16, padded
__device__ __half g_aggh[(NN + TILE_M) * IND];   // h_neigh * (1/32), fp16, padded
__device__ int   g_deg[NN];
__device__ int   g_ptr[NN];
__device__ int   g_cur[NN];
__device__ int   g_esrc[EE];
__device__ int   g_bsum[SCAN_NBLK];
__device__ int   g_boff[SCAN_NBLK];
__device__ float g_poolraw[GG * HID];
__device__ int   g_cnt[GG];
__device__ float g_bnstats[8 * HID];
__device__ float g_z1[GG * HID];
__device__ float g_z2[GG * HID];
__device__ float g_p[GG * HID];
__device__ __half g_Whi[256 * 256];              // W * 32, fp16 (single term)

// ---------------- helpers ----------------
__device__ __forceinline__ void redF1(float* addr, float v) {
    asm volatile("red.global.add.f32 [%0], %1;" :: "l"(addr), "f"(v) : "memory");
}
__device__ __forceinline__ void redI1(int* addr, int v) {
    asm volatile("red.global.add.s32 [%0], %1;" :: "l"(addr), "r"(v) : "memory");
}
__device__ __forceinline__ uint32_t smem_u32(const void* p) {
    uint32_t a;
    asm("{ .reg .u64 t; cvta.to.shared.u64 t, %1; cvt.u32.u64 %0, t; }"
        : "=r"(a) : "l"(p));
    return a;
}
__device__ __forceinline__ void ldsm4(uint32_t* r, uint32_t a) {
    asm volatile("ldmatrix.sync.aligned.m8n8.x4.shared.b16 {%0,%1,%2,%3}, [%4];"
        : "=r"(r[0]), "=r"(r[1]), "=r"(r[2]), "=r"(r[3]) : "r"(a));
}
__device__ __forceinline__ void ldsm4t(uint32_t* r, uint32_t a) {
    asm volatile("ldmatrix.sync.aligned.m8n8.x4.trans.shared.b16 {%0,%1,%2,%3}, [%4];"
        : "=r"(r[0]), "=r"(r[1]), "=r"(r[2]), "=r"(r[3]) : "r"(a));
}
__device__ __forceinline__ void mma16816(float* d, const uint32_t* a, const uint32_t* b) {
    asm volatile("mma.sync.aligned.m16n8k16.row.col.f32.f16.f16.f32 "
        "{%0,%1,%2,%3}, {%4,%5,%6,%7}, {%8,%9}, {%0,%1,%2,%3};"
        : "+f"(d[0]), "+f"(d[1]), "+f"(d[2]), "+f"(d[3])
        : "r"(a[0]), "r"(a[1]), "r"(a[2]), "r"(a[3]), "r"(b[0]), "r"(b[1]));
}
__device__ __forceinline__ void cpa16(uint32_t d, const void* s) {
    asm volatile("cp.async.cg.shared.global [%0], [%1], 16;" :: "r"(d), "l"(s));
}
__device__ __forceinline__ void cpa8(uint32_t d, const void* s) {
    asm volatile("cp.async.ca.shared.global [%0], [%1], 8;" :: "r"(d), "l"(s));
}
#define CP_COMMIT() asm volatile("cp.async.commit_group;" ::: "memory")
#define CP_WAIT0()  asm volatile("cp.async.wait_group 0;" ::: "memory")

// ---------------- K0: merged init — feat->fp16 image + W prep + zeros ----------
// (g_cnt accumulation happens in scan1_kernel, after this launch's zeroing.)
__global__ void init_kernel(const float* __restrict__ feat,
                            const float* __restrict__ W_self,
                            const float* __restrict__ W_neigh) {
    int idx = blockIdx.x * blockDim.x + threadIdx.x;
    // feat conversion: NN*32 uint2 units (the dominant sweep)
    if (idx < NN * (IND / 4)) {
        float4 v = __ldg(((const float4*)feat) + idx);
        __half h0 = __float2half(v.x * AINV);
        __half h1 = __float2half(v.y * AINV);
        __half h2 = __float2half(v.z * AINV);
        __half h3 = __float2half(v.w * AINV);
        uint2 u;
        u.x = ((uint32_t)__half_as_ushort(h1) << 16) | __half_as_ushort(h0);
        u.y = ((uint32_t)__half_as_ushort(h3) << 16) | __half_as_ushort(h2);
        ((uint2*)g_feath)[idx] = u;
    }
    if (idx < 65536) {
        int k = idx >> 8, n = idx & 255;
        float w = ((k < IND) ? W_self[k * HID + n] : W_neigh[(k - IND) * HID + n]) * WSCALE;
        g_Whi[idx] = __float2half(w);
    }
    if (idx < NN) g_deg[idx] = 0;
    if (idx < TILE_M * IND) {                          // zero pad rows
        g_feath[NN * IND + idx] = __ushort_as_half(0);
        g_aggh[NN * IND + idx] = __ushort_as_half(0);
    }
    if (idx < GG * HID) g_poolraw[idx] = 0.f;
    if (idx < GG) g_cnt[idx] = 0;
    if (idx < 6 * HID) g_bnstats[idx] = 0.f;
}

// ---------------- CSR phases ----------------
__global__ void deg_kernel(const int* __restrict__ dst) {
    int e = blockIdx.x * blockDim.x + threadIdx.x;
    if (e < EE) redI1(&g_deg[__ldg(&dst[e])], 1);
}

// scan1 also accumulates per-graph node counts (runs AFTER init zeroed g_cnt)
__global__ __launch_bounds__(SCAN_B) void scan1_kernel(const int* __restrict__ graph_id) {
    __shared__ int sh[SCAN_B];
    __shared__ int cnt[GG];
    int t = threadIdx.x;
    int i = blockIdx.x * SCAN_B + t;
    if (t < GG) cnt[t] = 0;
    sh[t] = (i < NN) ? g_deg[i] : 0;
    __syncthreads();
    if (i < NN) atomicAdd(&cnt[__ldg(&graph_id[i])], 1);
#pragma unroll
    for (int s = SCAN_B / 2; s > 0; s >>= 1) {
        if (t < s) sh[t] += sh[t + s];
        __syncthreads();
    }
    if (t == 0) g_bsum[blockIdx.x] = sh[0];
    if (t < GG && cnt[t]) redI1(&g_cnt[t], cnt[t]);
}

__global__ __launch_bounds__(128) void scan2_kernel() {
    __shared__ int sh[128];
    int t = threadIdx.x;
    int v = (t < SCAN_NBLK) ? g_bsum[t] : 0;
    sh[t] = v;
    __syncthreads();
#pragma unroll
    for (int off = 1; off < 128; off <<= 1) {
        int x = (t >= off) ? sh[t - off] : 0;
        __syncthreads();
        sh[t] += x;
        __syncthreads();
    }
    if (t < SCAN_NBLK) g_boff[t] = sh[t] - v;
}

__global__ __launch_bounds__(SCAN_B) void scan3_kernel() {
    __shared__ int sh[SCAN_B];
    int t = threadIdx.x;
    int i = blockIdx.x * SCAN_B + t;
    int v = (i < NN) ? g_deg[i] : 0;
    sh[t] = v;
    __syncthreads();
#pragma unroll
    for (int off = 1; off < SCAN_B; off <<= 1) {
        int x = (t >= off) ? sh[t - off] : 0;
        __syncthreads();
        sh[t] += x;
        __syncthreads();
    }
    if (i < NN) {
        int pos = g_boff[blockIdx.x] + sh[t] - v;
        g_ptr[i] = pos;
        g_cur[i] = pos;
    }
}

__global__ void fill_kernel(const int* __restrict__ src,
                            const int* __restrict__ dst) {
    int e = blockIdx.x * blockDim.x + threadIdx.x;
    if (e >= EE) return;
    int d = __ldg(&dst[e]);
    int pos = atomicAdd(&g_cur[d], 1);
    g_esrc[pos] = __ldg(&src[e]);
}

// ---------------- K1: gather-aggregate (warp per node, uniform esrc load) -------
__global__ __launch_bounds__(256) void agg_kernel() {
    int t = blockIdx.x * blockDim.x + threadIdx.x;
    int node = t >> 5;
    if (node >= NN) return;
    int lane = t & 31;
    int beg = __ldg(&g_ptr[node]);
    int d = __ldg(&g_deg[node]);
    float2 a0 = make_float2(0.f, 0.f), a1 = make_float2(0.f, 0.f);
    const uint2* base = (const uint2*)g_feath;   // 32 uint2 per row
    for (int i = 0; i < d; i++) {
        int s = __ldg(&g_esrc[beg + i]);
        uint2 u = __ldg(base + (size_t)s * 32 + lane);
        float2 f0 = __half22float2(*(__half2*)&u.x);
        float2 f1 = __half22float2(*(__half2*)&u.y);
        a0.x += f0.x; a0.y += f0.y; a1.x += f1.x; a1.y += f1.y;
    }
    float sc = 1.f / fmaxf((float)d, 1.f);       // feath already has the 1/32
    __half h0 = __float2half(a0.x * sc);
    __half h1 = __float2half(a0.y * sc);
    __half h2 = __float2half(a1.x * sc);
    __half h3 = __float2half(a1.y * sc);
    uint2 o;
    o.x = ((uint32_t)__half_as_ushort(h1) << 16) | __half_as_ushort(h0);
    o.y = ((uint32_t)__half_as_ushort(h3) << 16) | __half_as_ushort(h2);
    ((uint2*)g_aggh)[(size_t)node * 32 + lane] = o;
}

// ---------------- K2: mma.sync fp16 single-term GEMM, cp.async staged -----------
// stage: A [128][80B] @0 (10240), W [32][528B] @10240 (16896) => ST_SZ=27136,
// double buffered (54272). Epilogue aliases: C half[128][264] @0 (67584),
// colsum @67584, colsq @71680, pool @75776 (8192).
#define ST_SZ    27136
#define SOF_WH   10240
#define OFF_CS   67584
#define OFF_CQ   71680
#define OFF_POOL 75776
#define OFF_BSH  88064
#define OFF_GIDS 89088
#define OFF_GRNG 89600
#define DYN_SMEM 89616

__global__ __launch_bounds__(1024, 1) void conv_mma_kernel(
    const float* __restrict__ b_conv, const int* __restrict__ graph_id) {
    extern __shared__ char p0[];
    uint32_t sm = smem_u32(p0);
    float* s_bsh  = (float*)(p0 + OFF_BSH);
    int*   s_gids = (int*)(p0 + OFF_GIDS);
    int*   s_grng = (int*)(p0 + OFF_GRNG);

    int tid = threadIdx.x;
    int wid = tid >> 5;
    int lane = tid & 31;
    int row0 = blockIdx.x * TILE_M;

    if (tid < 256) s_bsh[tid] = b_conv[tid];
    if (tid < TILE_M) {
        int node = row0 + tid;
        s_gids[tid] = (node < NN) ? __ldg(&graph_id[node]) : -1;
    }
    __syncthreads();
    if (tid == 0) {
        int lo = s_gids[0], hi = lo;
#pragma unroll 1
        for (int i = 1; i < TILE_M; i++)
            if (s_gids[i] >= 0) hi = s_gids[i];
        s_grng[0] = lo; s_grng[1] = hi;
    }

    int wm = (wid >> 2) * 16;    // warp M offset (0..112)
    int wn = (wid & 3) * 64;     // warp N offset (0/64/128/192)

    float acc[8][4];
#pragma unroll
    for (int j = 0; j < 8; j++)
#pragma unroll
        for (int d = 0; d < 4; d++) acc[j][d] = 0.f;

    uint32_t Abase = sm + (wm + (lane & 15)) * 80 + (lane >> 4) * 16;
    uint32_t Bbase = sm + SOF_WH + (lane & 15) * 528 + (wn + (lane >> 4) * 8) * 2;

    auto stage = [&](int kc, int buf) {
        uint32_t st = sm + buf * ST_SZ;
        // A: 8B per thread (4 halfs), already fp16 pre-scaled
        {
            int r = tid >> 3, u = tid & 7;
            const __half* srcb = (kc < 4) ? g_feath : g_aggh;
            int kof = (kc & 3) * 32;
            cpa8(st + r * 80 + u * 8,
                 srcb + (size_t)(row0 + r) * IND + kof + u * 4);
        }
        // W: 16B per thread
        {
            int kk = tid >> 5, c = tid & 31;
            size_t so = (size_t)(kc * 32 + kk) * 256 + c * 8;
            cpa16(st + SOF_WH + kk * 528 + c * 16, g_Whi + so);
        }
    };
    auto compute = [&](int buf) {
        uint32_t so = buf * ST_SZ;
#pragma unroll
        for (int ks = 0; ks < 2; ks++) {
            uint32_t ab = Abase + so + ks * 32;
            uint32_t bb = Bbase + so + ks * 8448;   // ks*16*528
            uint32_t ah[4], f[4];
            ldsm4(ah, ab);
#pragma unroll
            for (int c = 0; c < 4; c++) {
                ldsm4t(f, bb + c * 32);
                mma16816(acc[2 * c], ah, f);
                mma16816(acc[2 * c + 1], ah, f + 2);
            }
        }
    };

    // -------- main loop: 8 K-chunks of 32, double-buffered cp.async --------
    stage(0, 0);
    CP_COMMIT();
    CP_WAIT0();
    __syncthreads();
#pragma unroll 1
    for (int kc = 0; kc < 8; kc++) {
        if (kc < 7) { stage(kc + 1, (kc + 1) & 1); CP_COMMIT(); }
        compute(kc & 1);
        if (kc < 7) CP_WAIT0();
        __syncthreads();
    }

    // -------- epilogue --------
    __half* C  = (__half*)p0;                 // [128][264]
    float* s_cs = (float*)(p0 + OFF_CS);      // [4][256]
    float* s_cq = (float*)(p0 + OFF_CQ);      // [4][256]
    float* s_pl = (float*)(p0 + OFF_POOL);    // [8][256]
#pragma unroll
    for (int j = 0; j < 8; j++) {
        int r0 = wm + (lane >> 2);
        int c = wn + j * 8 + (lane & 3) * 2;
        __half2 lo2 = __floats2half2_rn(acc[j][0], acc[j][1]);
        __half2 hi2 = __floats2half2_rn(acc[j][2], acc[j][3]);
        *(__half2*)&C[r0 * 264 + c] = lo2;
        *(__half2*)&C[(r0 + 8) * 264 + c] = hi2;
    }
    __syncthreads();
    // zero pool slots
    ((float*)s_pl)[tid] = 0.f;
    ((float*)s_pl)[tid + 1024] = 0.f;
    __syncthreads();

    int col = tid & 255, q = tid >> 8;        // quarter of rows (32 each)
    int glo = s_grng[0], ghi = s_grng[1];
    {
        float b = s_bsh[col];
        float sum = 0.f, sq = 0.f;
        int curg = -1;
        float run = 0.f;
#pragma unroll 4
        for (int rr = q * 32; rr < q * 32 + 32; rr++) {
            int gd = s_gids[rr];
            float v = __half2float(C[rr * 264 + col]) + b;
            v = (gd >= 0) ? fmaxf(v, 0.f) : 0.f;
            C[rr * 264 + col] = __float2half(v);
            sum += v; sq += v * v;
            if (gd != curg) {
                int slot = curg - glo;
                if (curg >= 0 && slot < 8) atomicAdd(&s_pl[slot * 256 + col], run);
                run = 0.f; curg = gd;
            }
            run += v;
        }
        int slot = curg - glo;
        if (curg >= 0 && slot < 8) atomicAdd(&s_pl[slot * 256 + col], run);
        s_cs[q * 256 + col] = sum;
        s_cq[q * 256 + col] = sq;
    }
    __syncthreads();
    if (tid < 256) {
        float s = s_cs[col] + s_cs[256 + col] + s_cs[512 + col] + s_cs[768 + col];
        redF1(&g_bnstats[col], s);
#pragma unroll 1
        for (int t = 0; t < 8; t++) {
            int g = glo + t;
            if (g <= ghi) redF1(&g_poolraw[g * HID + col], s_pl[t * 256 + col]);
        }
    } else if (tid < 512) {
        int c2 = tid - 256;
        float s = s_cq[c2] + s_cq[256 + c2] + s_cq[512 + c2] + s_cq[768 + c2];
        redF1(&g_bnstats[256 + c2], s);
    }
    // rare: block spans more than 8 graphs
#pragma unroll 1
    for (int p = 1; glo + 8 * p <= ghi; p++) {
        __syncthreads();
        ((float*)s_pl)[tid] = 0.f;
        ((float*)s_pl)[tid + 1024] = 0.f;
        __syncthreads();
        int base = glo + 8 * p;
        int curg = -1;
        float run = 0.f;
#pragma unroll 1
        for (int rr = q * 32; rr < q * 32 + 32; rr++) {
            int gd = s_gids[rr];
            float v = __half2float(C[rr * 264 + col]);
            if (gd != curg) {
                int slot = curg - base;
                if (slot >= 0 && slot < 8) atomicAdd(&s_pl[slot * 256 + col], run);
                run = 0.f; curg = gd;
            }
            run += v;
        }
        int slot = curg - base;
        if (slot >= 0 && slot < 8) atomicAdd(&s_pl[slot * 256 + col], run);
        __syncthreads();
        if (tid < 256) {
#pragma unroll 1
            for (int t = 0; t < 8; t++) {
                int g = base + t;
                if (g <= ghi) redF1(&g_poolraw[g * HID + col], s_pl[t * 256 + col]);
            }
        }
    }
}

// ---------------- K4: z1 = relu(pooled @ W_lp + b) + stats (BN fold inline) -------
__global__ __launch_bounds__(HID) void lp1_kernel(const float* __restrict__ W_lp,
                                                  const float* __restrict__ b_lp,
                                                  const float* __restrict__ gamma,
                                                  const float* __restrict__ beta) {
    __shared__ float row[HID];
    int g = blockIdx.x, c = threadIdx.x;
    float mean = g_bnstats[c] * (1.0f / NN);
    float var  = g_bnstats[256 + c] * (1.0f / NN) - mean * mean;
    float sc = gamma[c] * rsqrtf(var + BN_EPS);
    float sh = beta[c] - mean * sc;
    float cntf = (float)g_cnt[g];
    row[c] = fmaf(g_poolraw[g * HID + c], sc, cntf * sh);
    __syncthreads();
    float acc = b_lp[c];
#pragma unroll 8
    for (int k = 0; k < HID; k++) acc = fmaf(row[k], __ldg(&W_lp[k * HID + c]), acc);
    float r = fmaxf(acc, 0.f);
    g_z1[g * HID + c] = r;
    atomicAdd(&g_bnstats[512 + c], r);
    atomicAdd(&g_bnstats[768 + c], r * r);
}

// ---------------- K5: BN(z1) -> p, z2 = relu(p @ W_lp + b) + stats ----------------
__global__ __launch_bounds__(HID) void lp2_kernel(const float* __restrict__ W_lp,
                                                  const float* __restrict__ b_lp,
                                                  const float* __restrict__ gamma,
                                                  const float* __restrict__ beta,
                                                  float* __restrict__ out_p) {
    __shared__ float row[HID];
    int g = blockIdx.x, c = threadIdx.x;
    float r = g_z1[g * HID + c];
    float mean = g_bnstats[512 + c] * (1.f / GG);
    float var  = g_bnstats[768 + c] * (1.f / GG) - mean * mean;
    float p = (r - mean) * rsqrtf(var + BN_EPS) * gamma[c] + beta[c];
    out_p[g * HID + c] = p;
    row[c] = p;
    __syncthreads();
    float acc = b_lp[c];
#pragma unroll 8
    for (int k = 0; k < HID; k++) acc = fmaf(row[k], __ldg(&W_lp[k * HID + c]), acc);
    float r2 = fmaxf(acc, 0.f);
    g_z2[g * HID + c] = r2;
    atomicAdd(&g_bnstats[1024 + c], r2);
    atomicAdd(&g_bnstats[1280 + c], r2 * r2);
}

// ---------------- K6: BN(z2) + log_softmax ----------------
__global__ __launch_bounds__(HID) void lp3_kernel(const float* __restrict__ gamma,
                                                  const float* __restrict__ beta,
                                                  float* __restrict__ out) {
    __shared__ float buf[HID];
    int g = blockIdx.x, c = threadIdx.x;
    float r = g_z2[g * HID + c];
    float mean = g_bnstats[1024 + c] * (1.f / GG);
    float var  = g_bnstats[1280 + c] * (1.f / GG) - mean * mean;
    float o = (r - mean) * rsqrtf(var + BN_EPS) * gamma[c] + beta[c];
    buf[c] = o;
    __syncthreads();
    for (int s = 128; s > 0; s >>= 1) {
        if (c < s) buf[c] = fmaxf(buf[c], buf[c + s]);
        __syncthreads();
    }
    float m = buf[0];
    __syncthreads();
    float e = expf(o - m);
    buf[c] = e;
    __syncthreads();
    for (int s = 128; s > 0; s >>= 1) {
        if (c < s) buf[c] += buf[c + s];
        __syncthreads();
    }
    float lse = logf(buf[0]);
    out[g * HID + c] = o - m - lse;
}

// ---------------- launch ----------------
extern "C" void kernel_launch(void* const* d_in, const int* in_sizes, int n_in,
                              void* d_out, int out_size) {
    const float* feat       = (const float*)d_in[0];
    const float* W_self     = (const float*)d_in[1];
    const float* W_neigh    = (const float*)d_in[2];
    const float* b_conv     = (const float*)d_in[3];
    const float* gamma_conv = (const float*)d_in[4];
    const float* beta_conv  = (const float*)d_in[5];
    const float* W_lp       = (const float*)d_in[6];
    const float* b_lp       = (const float*)d_in[7];
    const float* gamma_lp   = (const float*)d_in[8];
    const float* beta_lp    = (const float*)d_in[9];
    const int*   src        = (const int*)d_in[10];
    const int*   dst        = (const int*)d_in[11];
    const int*   graph_id   = (const int*)d_in[12];
    float* out = (float*)d_out;

    float* out_p;
    if (out_size >= 2 * GG * HID) {
        out_p = out + GG * HID;
    } else {
        void* pp = nullptr;
        cudaGetSymbolAddress(&pp, g_p);
        out_p = (float*)pp;
    }

    cudaFuncSetAttribute(conv_mma_kernel,
                         cudaFuncAttributeMaxDynamicSharedMemorySize, DYN_SMEM);

    init_kernel<<<(NN * (IND / 4) + 255) / 256, 256>>>(feat, W_self, W_neigh);
    deg_kernel<<<(EE + 255) / 256, 256>>>(dst);
    scan1_kernel<<<SCAN_NBLK, SCAN_B>>>(graph_id);
    scan2_kernel<<<1, 128>>>();
    scan3_kernel<<<SCAN_NBLK, SCAN_B>>>();
    fill_kernel<<<(EE + 255) / 256, 256>>>(src, dst);
    agg_kernel<<<(NN * 32 + 255) / 256, 256>>>();
    conv_mma_kernel<<<MBLK, 1024, DYN_SMEM>>>(b_conv, graph_id);
    lp1_kernel<<<GG, HID>>>(W_lp, b_lp, gamma_conv, beta_conv);
    lp2_kernel<<<GG, HID>>>(W_lp, b_lp, gamma_lp, beta_lp, out_p);
    lp3_kernel<<<GG, HID>>>(gamma_lp, beta_lp, out);
}

// round 15
// speedup vs baseline: 1.4667x; 1.0143x over previous
#include <cuda_runtime.h>
#include <cuda_fp16.h>
#include <cstdint>

#define NN  100000
#define EE  1000000
#define IND 128
#define HID 256
#define GG  64
#define BN_EPS 1e-5f

#define SCAN_B 1024
#define SCAN_NBLK ((NN + SCAN_B - 1) / SCAN_B)   // 98

#define TILE_M 128
#define MBLK ((NN + TILE_M - 1) / TILE_M)        // 782

#define WSCALE 32.0f
#define AINV   0.03125f

// ---------------- scratch (static device globals; no allocation) ----------------
__device__ __half g_feath[(NN + TILE_M) * IND];  // feat * (1/32), fp16, padded
__device__ __half g_aggh[(NN + TILE_M) * IND];   // h_neigh * (1/32), fp16, padded
__device__ int   g_deg[NN];
__device__ int   g_ptr[NN];
__device__ int   g_cur[NN];
__device__ int   g_esrc[EE];
__device__ int   g_bsum[SCAN_NBLK];
__device__ float g_poolraw[GG * HID];
__device__ int   g_cnt[GG];
__device__ float g_bnstats[8 * HID];
__device__ float g_p[GG * HID];
__device__ int   g_bar1, g_bar2;
__device__ __half g_Whi[256 * 256];              // W * 32, fp16 (single term)

// ---------------- helpers ----------------
__device__ __forceinline__ void redF1(float* addr, float v) {
    asm volatile("red.global.add.f32 [%0], %1;" :: "l"(addr), "f"(v) : "memory");
}
__device__ __forceinline__ void redI1(int* addr, int v) {
    asm volatile("red.global.add.s32 [%0], %1;" :: "l"(addr), "r"(v) : "memory");
}
__device__ __forceinline__ uint32_t smem_u32(const void* p) {
    uint32_t a;
    asm("{ .reg .u64 t; cvta.to.shared.u64 t, %1; cvt.u32.u64 %0, t; }"
        : "=r"(a) : "l"(p));
    return a;
}
__device__ __forceinline__ void ldsm4(uint32_t* r, uint32_t a) {
    asm volatile("ldmatrix.sync.aligned.m8n8.x4.shared.b16 {%0,%1,%2,%3}, [%4];"
        : "=r"(r[0]), "=r"(r[1]), "=r"(r[2]), "=r"(r[3]) : "r"(a));
}
__device__ __forceinline__ void ldsm4t(uint32_t* r, uint32_t a) {
    asm volatile("ldmatrix.sync.aligned.m8n8.x4.trans.shared.b16 {%0,%1,%2,%3}, [%4];"
        : "=r"(r[0]), "=r"(r[1]), "=r"(r[2]), "=r"(r[3]) : "r"(a));
}
__device__ __forceinline__ void mma16816(float* d, const uint32_t* a, const uint32_t* b) {
    asm volatile("mma.sync.aligned.m16n8k16.row.col.f32.f16.f16.f32 "
        "{%0,%1,%2,%3}, {%4,%5,%6,%7}, {%8,%9}, {%0,%1,%2,%3};"
        : "+f"(d[0]), "+f"(d[1]), "+f"(d[2]), "+f"(d[3])
        : "r"(a[0]), "r"(a[1]), "r"(a[2]), "r"(a[3]), "r"(b[0]), "r"(b[1]));
}
__device__ __forceinline__ void cpa16(uint32_t d, const void* s) {
    asm volatile("cp.async.cg.shared.global [%0], [%1], 16;" :: "r"(d), "l"(s));
}
__device__ __forceinline__ void cpa8(uint32_t d, const void* s) {
    asm volatile("cp.async.ca.shared.global [%0], [%1], 8;" :: "r"(d), "l"(s));
}
#define CP_COMMIT() asm volatile("cp.async.commit_group;" ::: "memory")
#define CP_WAIT0()  asm volatile("cp.async.wait_group 0;" ::: "memory")

// ---------------- K0: merged init — feat->fp16 image + W prep + zeros ----------
__global__ void init_kernel(const float* __restrict__ feat,
                            const float* __restrict__ W_self,
                            const float* __restrict__ W_neigh) {
    int idx = blockIdx.x * blockDim.x + threadIdx.x;
    if (idx < NN * (IND / 4)) {
        float4 v = __ldg(((const float4*)feat) + idx);
        __half h0 = __float2half(v.x * AINV);
        __half h1 = __float2half(v.y * AINV);
        __half h2 = __float2half(v.z * AINV);
        __half h3 = __float2half(v.w * AINV);
        uint2 u;
        u.x = ((uint32_t)__half_as_ushort(h1) << 16) | __half_as_ushort(h0);
        u.y = ((uint32_t)__half_as_ushort(h3) << 16) | __half_as_ushort(h2);
        ((uint2*)g_feath)[idx] = u;
    }
    if (idx < 65536) {
        int k = idx >> 8, n = idx & 255;
        float w = ((k < IND) ? W_self[k * HID + n] : W_neigh[(k - IND) * HID + n]) * WSCALE;
        g_Whi[idx] = __float2half(w);
    }
    if (idx < NN) g_deg[idx] = 0;
    if (idx < TILE_M * IND) {                          // zero pad rows
        g_feath[NN * IND + idx] = __ushort_as_half(0);
        g_aggh[NN * IND + idx] = __ushort_as_half(0);
    }
    if (idx < GG * HID) g_poolraw[idx] = 0.f;
    if (idx < GG) g_cnt[idx] = 0;
    if (idx < 6 * HID) g_bnstats[idx] = 0.f;
    if (idx == 0) { g_bar1 = 0; g_bar2 = 0; }
}

// ---------------- CSR phases ----------------
__global__ void deg_kernel(const int* __restrict__ dst) {
    int e = blockIdx.x * blockDim.x + threadIdx.x;
    if (e < EE) redI1(&g_deg[__ldg(&dst[e])], 1);
}

// scan1 also accumulates per-graph node counts (runs AFTER init zeroed g_cnt)
__global__ __launch_bounds__(SCAN_B) void scan1_kernel(const int* __restrict__ graph_id) {
    __shared__ int sh[SCAN_B];
    __shared__ int cnt[GG];
    int t = threadIdx.x;
    int i = blockIdx.x * SCAN_B + t;
    if (t < GG) cnt[t] = 0;
    sh[t] = (i < NN) ? g_deg[i] : 0;
    __syncthreads();
    if (i < NN) atomicAdd(&cnt[__ldg(&graph_id[i])], 1);
#pragma unroll
    for (int s = SCAN_B / 2; s > 0; s >>= 1) {
        if (t < s) sh[t] += sh[t + s];
        __syncthreads();
    }
    if (t == 0) g_bsum[blockIdx.x] = sh[0];
    if (t < GG && cnt[t]) redI1(&g_cnt[t], cnt[t]);
}

// scan3 computes its own block offset from g_bsum (scan2 deleted)
__global__ __launch_bounds__(SCAN_B) void scan3_kernel() {
    __shared__ int sh[SCAN_B];
    __shared__ int offs[128];
    int t = threadIdx.x;
    int i = blockIdx.x * SCAN_B + t;
    if (t < 128)
        offs[t] = (t < blockIdx.x && t < SCAN_NBLK) ? g_bsum[t] : 0;
    int v = (i < NN) ? g_deg[i] : 0;
    sh[t] = v;
    __syncthreads();
#pragma unroll
    for (int s = 64; s > 0; s >>= 1) {
        if (t < s) offs[t] += offs[t + s];
        __syncthreads();
    }
    int boff = offs[0];
#pragma unroll
    for (int off = 1; off < SCAN_B; off <<= 1) {
        int x = (t >= off) ? sh[t - off] : 0;
        __syncthreads();
        sh[t] += x;
        __syncthreads();
    }
    if (i < NN) {
        int pos = boff + sh[t] - v;     // exclusive
        g_ptr[i] = pos;
        g_cur[i] = pos;
    }
}

__global__ void fill_kernel(const int* __restrict__ src,
                            const int* __restrict__ dst) {
    int e = blockIdx.x * blockDim.x + threadIdx.x;
    if (e >= EE) return;
    int d = __ldg(&dst[e]);
    int pos = atomicAdd(&g_cur[d], 1);
    g_esrc[pos] = __ldg(&src[e]);
}

// ---------------- K1: gather-aggregate (warp per node, uniform esrc load) -------
__global__ __launch_bounds__(256) void agg_kernel() {
    int t = blockIdx.x * blockDim.x + threadIdx.x;
    int node = t >> 5;
    if (node >= NN) return;
    int lane = t & 31;
    int beg = __ldg(&g_ptr[node]);
    int d = __ldg(&g_deg[node]);
    float2 a0 = make_float2(0.f, 0.f), a1 = make_float2(0.f, 0.f);
    const uint2* base = (const uint2*)g_feath;   // 32 uint2 per row
    for (int i = 0; i < d; i++) {
        int s = __ldg(&g_esrc[beg + i]);
        uint2 u = __ldg(base + (size_t)s * 32 + lane);
        float2 f0 = __half22float2(*(__half2*)&u.x);
        float2 f1 = __half22float2(*(__half2*)&u.y);
        a0.x += f0.x; a0.y += f0.y; a1.x += f1.x; a1.y += f1.y;
    }
    float sc = 1.f / fmaxf((float)d, 1.f);       // feath already has the 1/32
    __half h0 = __float2half(a0.x * sc);
    __half h1 = __float2half(a0.y * sc);
    __half h2 = __float2half(a1.x * sc);
    __half h3 = __float2half(a1.y * sc);
    uint2 o;
    o.x = ((uint32_t)__half_as_ushort(h1) << 16) | __half_as_ushort(h0);
    o.y = ((uint32_t)__half_as_ushort(h3) << 16) | __half_as_ushort(h2);
    ((uint2*)g_aggh)[(size_t)node * 32 + lane] = o;
}

// ---------------- K2: mma.sync fp16 single-term GEMM, cp.async staged -----------
#define ST_SZ    27136
#define SOF_WH   10240
#define OFF_CS   67584
#define OFF_CQ   71680
#define OFF_POOL 75776
#define OFF_BSH  88064
#define OFF_GIDS 89088
#define OFF_GRNG 89600
#define DYN_SMEM 89616

__global__ __launch_bounds__(1024, 1) void conv_mma_kernel(
    const float* __restrict__ b_conv, const int* __restrict__ graph_id) {
    extern __shared__ char p0[];
    uint32_t sm = smem_u32(p0);
    float* s_bsh  = (float*)(p0 + OFF_BSH);
    int*   s_gids = (int*)(p0 + OFF_GIDS);
    int*   s_grng = (int*)(p0 + OFF_GRNG);

    int tid = threadIdx.x;
    int wid = tid >> 5;
    int lane = tid & 31;
    int row0 = blockIdx.x * TILE_M;

    if (tid < 256) s_bsh[tid] = b_conv[tid];
    if (tid < TILE_M) {
        int node = row0 + tid;
        s_gids[tid] = (node < NN) ? __ldg(&graph_id[node]) : -1;
    }
    __syncthreads();
    if (tid == 0) {
        int lo = s_gids[0], hi = lo;
#pragma unroll 1
        for (int i = 1; i < TILE_M; i++)
            if (s_gids[i] >= 0) hi = s_gids[i];
        s_grng[0] = lo; s_grng[1] = hi;
    }

    int wm = (wid >> 2) * 16;    // warp M offset (0..112)
    int wn = (wid & 3) * 64;     // warp N offset (0/64/128/192)

    float acc[8][4];
#pragma unroll
    for (int j = 0; j < 8; j++)
#pragma unroll
        for (int d = 0; d < 4; d++) acc[j][d] = 0.f;

    uint32_t Abase = sm + (wm + (lane & 15)) * 80 + (lane >> 4) * 16;
    uint32_t Bbase = sm + SOF_WH + (lane & 15) * 528 + (wn + (lane >> 4) * 8) * 2;

    auto stage = [&](int kc, int buf) {
        uint32_t st = sm + buf * ST_SZ;
        {
            int r = tid >> 3, u = tid & 7;
            const __half* srcb = (kc < 4) ? g_feath : g_aggh;
            int kof = (kc & 3) * 32;
            cpa8(st + r * 80 + u * 8,
                 srcb + (size_t)(row0 + r) * IND + kof + u * 4);
        }
        {
            int kk = tid >> 5, c = tid & 31;
            size_t so = (size_t)(kc * 32 + kk) * 256 + c * 8;
            cpa16(st + SOF_WH + kk * 528 + c * 16, g_Whi + so);
        }
    };
    auto compute = [&](int buf) {
        uint32_t so = buf * ST_SZ;
#pragma unroll
        for (int ks = 0; ks < 2; ks++) {
            uint32_t ab = Abase + so + ks * 32;
            uint32_t bb = Bbase + so + ks * 8448;   // ks*16*528
            uint32_t ah[4], f[4];
            ldsm4(ah, ab);
#pragma unroll
            for (int c = 0; c < 4; c++) {
                ldsm4t(f, bb + c * 32);
                mma16816(acc[2 * c], ah, f);
                mma16816(acc[2 * c + 1], ah, f + 2);
            }
        }
    };

    stage(0, 0);
    CP_COMMIT();
    CP_WAIT0();
    __syncthreads();
#pragma unroll 1
    for (int kc = 0; kc < 8; kc++) {
        if (kc < 7) { stage(kc + 1, (kc + 1) & 1); CP_COMMIT(); }
        compute(kc & 1);
        if (kc < 7) CP_WAIT0();
        __syncthreads();
    }

    // -------- epilogue --------
    __half* C  = (__half*)p0;                 // [128][264]
    float* s_cs = (float*)(p0 + OFF_CS);      // [4][256]
    float* s_cq = (float*)(p0 + OFF_CQ);      // [4][256]
    float* s_pl = (float*)(p0 + OFF_POOL);    // [8][256]
#pragma unroll
    for (int j = 0; j < 8; j++) {
        int r0 = wm + (lane >> 2);
        int c = wn + j * 8 + (lane & 3) * 2;
        __half2 lo2 = __floats2half2_rn(acc[j][0], acc[j][1]);
        __half2 hi2 = __floats2half2_rn(acc[j][2], acc[j][3]);
        *(__half2*)&C[r0 * 264 + c] = lo2;
        *(__half2*)&C[(r0 + 8) * 264 + c] = hi2;
    }
    __syncthreads();
    ((float*)s_pl)[tid] = 0.f;
    ((float*)s_pl)[tid + 1024] = 0.f;
    __syncthreads();

    int col = tid & 255, q = tid >> 8;
    int glo = s_grng[0], ghi = s_grng[1];
    {
        float b = s_bsh[col];
        float sum = 0.f, sq = 0.f;
        int curg = -1;
        float run = 0.f;
#pragma unroll 4
        for (int rr = q * 32; rr < q * 32 + 32; rr++) {
            int gd = s_gids[rr];
            float v = __half2float(C[rr * 264 + col]) + b;
            v = (gd >= 0) ? fmaxf(v, 0.f) : 0.f;
            C[rr * 264 + col] = __float2half(v);
            sum += v; sq += v * v;
            if (gd != curg) {
                int slot = curg - glo;
                if (curg >= 0 && slot < 8) atomicAdd(&s_pl[slot * 256 + col], run);
                run = 0.f; curg = gd;
            }
            run += v;
        }
        int slot = curg - glo;
        if (curg >= 0 && slot < 8) atomicAdd(&s_pl[slot * 256 + col], run);
        s_cs[q * 256 + col] = sum;
        s_cq[q * 256 + col] = sq;
    }
    __syncthreads();
    if (tid < 256) {
        float s = s_cs[col] + s_cs[256 + col] + s_cs[512 + col] + s_cs[768 + col];
        redF1(&g_bnstats[col], s);
#pragma unroll 1
        for (int t = 0; t < 8; t++) {
            int g = glo + t;
            if (g <= ghi) redF1(&g_poolraw[g * HID + col], s_pl[t * 256 + col]);
        }
    } else if (tid < 512) {
        int c2 = tid - 256;
        float s = s_cq[c2] + s_cq[256 + c2] + s_cq[512 + c2] + s_cq[768 + c2];
        redF1(&g_bnstats[256 + c2], s);
    }
#pragma unroll 1
    for (int p = 1; glo + 8 * p <= ghi; p++) {
        __syncthreads();
        ((float*)s_pl)[tid] = 0.f;
        ((float*)s_pl)[tid + 1024] = 0.f;
        __syncthreads();
        int base = glo + 8 * p;
        int curg = -1;
        float run = 0.f;
#pragma unroll 1
        for (int rr = q * 32; rr < q * 32 + 32; rr++) {
            int gd = s_gids[rr];
            float v = __half2float(C[rr * 264 + col]);
            if (gd != curg) {
                int slot = curg - base;
                if (slot >= 0 && slot < 8) atomicAdd(&s_pl[slot * 256 + col], run);
                run = 0.f; curg = gd;
            }
            run += v;
        }
        int slot = curg - base;
        if (slot >= 0 && slot < 8) atomicAdd(&s_pl[slot * 256 + col], run);
        __syncthreads();
        if (tid < 256) {
#pragma unroll 1
            for (int t = 0; t < 8; t++) {
                int g = base + t;
                if (g <= ghi) redF1(&g_poolraw[g * HID + col], s_pl[t * 256 + col]);
            }
        }
    }
}

// ---------------- K4: merged head — lp1+lp2+lp3 with software grid barriers ------
// Grid is exactly GG=64 blocks x 256 threads: all blocks co-resident (148 SMs),
// so tid-0 spin barriers cannot deadlock. Stats published via red.global (L2);
// post-barrier reads use __ldcg (L1 bypass).
__global__ __launch_bounds__(HID) void head_kernel(
    const float* __restrict__ W_lp, const float* __restrict__ b_lp,
    const float* __restrict__ gamma_c, const float* __restrict__ beta_c,
    const float* __restrict__ gamma_lp, const float* __restrict__ beta_lp,
    float* __restrict__ out_p, float* __restrict__ out) {
    __shared__ float row[HID];
    int g = blockIdx.x, c = threadIdx.x;

    // phase 1: pooled (BN-conv folded) -> z1 = relu(pooled @ W + b), stats
    float mean = g_bnstats[c] * (1.0f / NN);
    float var  = g_bnstats[256 + c] * (1.0f / NN) - mean * mean;
    float sc = gamma_c[c] * rsqrtf(var + BN_EPS);
    float sh = beta_c[c] - mean * sc;
    float cntf = (float)g_cnt[g];
    row[c] = fmaf(g_poolraw[g * HID + c], sc, cntf * sh);
    __syncthreads();
    float acc = b_lp[c];
#pragma unroll 8
    for (int k = 0; k < HID; k++) acc = fmaf(row[k], __ldg(&W_lp[k * HID + c]), acc);
    float r = fmaxf(acc, 0.f);
    redF1(&g_bnstats[512 + c], r);
    redF1(&g_bnstats[768 + c], r * r);
    __threadfence();
    __syncthreads();
    if (c == 0) {
        atomicAdd(&g_bar1, 1);
        while (atomicAdd(&g_bar1, 0) < GG) { }
    }
    __syncthreads();

    // phase 2: p = BN(z1), out_p; z2 = relu(p @ W + b), stats
    float m1 = __ldcg(&g_bnstats[512 + c]) * (1.f / GG);
    float v1 = __ldcg(&g_bnstats[768 + c]) * (1.f / GG) - m1 * m1;
    float p = (r - m1) * rsqrtf(v1 + BN_EPS) * gamma_lp[c] + beta_lp[c];
    out_p[g * HID + c] = p;
    row[c] = p;
    __syncthreads();
    acc = b_lp[c];
#pragma unroll 8
    for (int k = 0; k < HID; k++) acc = fmaf(row[k], __ldg(&W_lp[k * HID + c]), acc);
    float r2 = fmaxf(acc, 0.f);
    redF1(&g_bnstats[1024 + c], r2);
    redF1(&g_bnstats[1280 + c], r2 * r2);
    __threadfence();
    __syncthreads();
    if (c == 0) {
        atomicAdd(&g_bar2, 1);
        while (atomicAdd(&g_bar2, 0) < GG) { }
    }
    __syncthreads();

    // phase 3: BN(z2) + log_softmax
    float m2 = __ldcg(&g_bnstats[1024 + c]) * (1.f / GG);
    float v2 = __ldcg(&g_bnstats[1280 + c]) * (1.f / GG) - m2 * m2;
    float o = (r2 - m2) * rsqrtf(v2 + BN_EPS) * gamma_lp[c] + beta_lp[c];
    row[c] = o;
    __syncthreads();
    for (int s = 128; s > 0; s >>= 1) {
        if (c < s) row[c] = fmaxf(row[c], row[c + s]);
        __syncthreads();
    }
    float mx = row[0];
    __syncthreads();
    float e = expf(o - mx);
    row[c] = e;
    __syncthreads();
    for (int s = 128; s > 0; s >>= 1) {
        if (c < s) row[c] += row[c + s];
        __syncthreads();
    }
    float lse = logf(row[0]);
    out[g * HID + c] = o - mx - lse;
}

// ---------------- launch ----------------
extern "C" void kernel_launch(void* const* d_in, const int* in_sizes, int n_in,
                              void* d_out, int out_size) {
    const float* feat       = (const float*)d_in[0];
    const float* W_self     = (const float*)d_in[1];
    const float* W_neigh    = (const float*)d_in[2];
    const float* b_conv     = (const float*)d_in[3];
    const float* gamma_conv = (const float*)d_in[4];
    const float* beta_conv  = (const float*)d_in[5];
    const float* W_lp       = (const float*)d_in[6];
    const float* b_lp       = (const float*)d_in[7];
    const float* gamma_lp   = (const float*)d_in[8];
    const float* beta_lp    = (const float*)d_in[9];
    const int*   src        = (const int*)d_in[10];
    const int*   dst        = (const int*)d_in[11];
    const int*   graph_id   = (const int*)d_in[12];
    float* out = (float*)d_out;

    float* out_p;
    if (out_size >= 2 * GG * HID) {
        out_p = out + GG * HID;
    } else {
        void* pp = nullptr;
        cudaGetSymbolAddress(&pp, g_p);
        out_p = (float*)pp;
    }

    cudaFuncSetAttribute(conv_mma_kernel,
                         cudaFuncAttributeMaxDynamicSharedMemorySize, DYN_SMEM);

    init_kernel<<<(NN * (IND / 4) + 255) / 256, 256>>>(feat, W_self, W_neigh);
    deg_kernel<<<(EE + 255) / 256, 256>>>(dst);
    scan1_kernel<<<SCAN_NBLK, SCAN_B>>>(graph_id);
    scan3_kernel<<<SCAN_NBLK, SCAN_B>>>();
    fill_kernel<<<(EE + 255) / 256, 256>>>(src, dst);
    agg_kernel<<<(NN * 32 + 255) / 256, 256>>>();
    conv_mma_kernel<<<MBLK, 1024, DYN_SMEM>>>(b_conv, graph_id);
    head_kernel<<<GG, HID>>>(W_lp, b_lp, gamma_conv, beta_conv,
                             gamma_lp, beta_lp, out_p, out);
}

// round 16
// speedup vs baseline: 1.4691x; 1.0016x over previous
#include <cuda_runtime.h>
#include <cuda_fp16.h>
#include <cstdint>

#define NN  100000
#define EE  1000000
#define IND 128
#define HID 256
#define GG  64
#define BN_EPS 1e-5f

#define SCAN_B 1024
#define SCAN_NBLK ((NN + SCAN_B - 1) / SCAN_B)   // 98

#define TILE_M 128
#define MBLK ((NN + TILE_M - 1) / TILE_M)        // 782

#define WSCALE 32.0f
#define AINV   0.03125f

// ---------------- scratch (static device globals; no allocation) ----------------
__device__ __half g_feath[(NN + TILE_M) * IND];  // feat * (1/32), fp16, padded
__device__ __half g_aggh[(NN + TILE_M) * IND];   // h_neigh * (1/32), fp16, padded
__device__ int   g_deg[NN];
__device__ int   g_ptr[NN];
__device__ int   g_cur[NN];
__device__ int   g_esrc[EE];
__device__ int   g_bsum[SCAN_NBLK];
__device__ float g_poolraw[GG * HID];
__device__ int   g_cnt[GG];
__device__ float g_bnstats[8 * HID];
__device__ float g_p[GG * HID];
__device__ int   g_bar1, g_bar2;
__device__ __half g_Whi[256 * 256];              // W * 32, fp16 (single term)

// ---------------- helpers ----------------
__device__ __forceinline__ void redF1(float* addr, float v) {
    asm volatile("red.global.add.f32 [%0], %1;" :: "l"(addr), "f"(v) : "memory");
}
__device__ __forceinline__ void redI1(int* addr, int v) {
    asm volatile("red.global.add.s32 [%0], %1;" :: "l"(addr), "r"(v) : "memory");
}
__device__ __forceinline__ uint32_t smem_u32(const void* p) {
    uint32_t a;
    asm("{ .reg .u64 t; cvta.to.shared.u64 t, %1; cvt.u32.u64 %0, t; }"
        : "=r"(a) : "l"(p));
    return a;
}
__device__ __forceinline__ void ldsm4(uint32_t* r, uint32_t a) {
    asm volatile("ldmatrix.sync.aligned.m8n8.x4.shared.b16 {%0,%1,%2,%3}, [%4];"
        : "=r"(r[0]), "=r"(r[1]), "=r"(r[2]), "=r"(r[3]) : "r"(a));
}
__device__ __forceinline__ void ldsm4t(uint32_t* r, uint32_t a) {
    asm volatile("ldmatrix.sync.aligned.m8n8.x4.trans.shared.b16 {%0,%1,%2,%3}, [%4];"
        : "=r"(r[0]), "=r"(r[1]), "=r"(r[2]), "=r"(r[3]) : "r"(a));
}
__device__ __forceinline__ void mma16816(float* d, const uint32_t* a, const uint32_t* b) {
    asm volatile("mma.sync.aligned.m16n8k16.row.col.f32.f16.f16.f32 "
        "{%0,%1,%2,%3}, {%4,%5,%6,%7}, {%8,%9}, {%0,%1,%2,%3};"
        : "+f"(d[0]), "+f"(d[1]), "+f"(d[2]), "+f"(d[3])
        : "r"(a[0]), "r"(a[1]), "r"(a[2]), "r"(a[3]), "r"(b[0]), "r"(b[1]));
}
__device__ __forceinline__ void cpa16(uint32_t d, const void* s) {
    asm volatile("cp.async.cg.shared.global [%0], [%1], 16;" :: "r"(d), "l"(s));
}
__device__ __forceinline__ void cpa8(uint32_t d, const void* s) {
    asm volatile("cp.async.ca.shared.global [%0], [%1], 8;" :: "r"(d), "l"(s));
}
#define CP_COMMIT() asm volatile("cp.async.commit_group;" ::: "memory")
#define CP_WAIT0()  asm volatile("cp.async.wait_group 0;" ::: "memory")
#define CP_WAIT1()  asm volatile("cp.async.wait_group 1;" ::: "memory")

// ---------------- K0: merged init — feat->fp16 image + W prep + zeros ----------
__global__ void init_kernel(const float* __restrict__ feat,
                            const float* __restrict__ W_self,
                            const float* __restrict__ W_neigh) {
    int idx = blockIdx.x * blockDim.x + threadIdx.x;
    if (idx < NN * (IND / 4)) {
        float4 v = __ldg(((const float4*)feat) + idx);
        __half h0 = __float2half(v.x * AINV);
        __half h1 = __float2half(v.y * AINV);
        __half h2 = __float2half(v.z * AINV);
        __half h3 = __float2half(v.w * AINV);
        uint2 u;
        u.x = ((uint32_t)__half_as_ushort(h1) << 16) | __half_as_ushort(h0);
        u.y = ((uint32_t)__half_as_ushort(h3) << 16) | __half_as_ushort(h2);
        ((uint2*)g_feath)[idx] = u;
    }
    if (idx < 65536) {
        int k = idx >> 8, n = idx & 255;
        float w = ((k < IND) ? W_self[k * HID + n] : W_neigh[(k - IND) * HID + n]) * WSCALE;
        g_Whi[idx] = __float2half(w);
    }
    if (idx < NN) g_deg[idx] = 0;
    if (idx < TILE_M * IND) {                          // zero pad rows
        g_feath[NN * IND + idx] = __ushort_as_half(0);
        g_aggh[NN * IND + idx] = __ushort_as_half(0);
    }
    if (idx < GG * HID) g_poolraw[idx] = 0.f;
    if (idx < GG) g_cnt[idx] = 0;
    if (idx < 6 * HID) g_bnstats[idx] = 0.f;
    if (idx == 0) { g_bar1 = 0; g_bar2 = 0; }
}

// ---------------- CSR phases ----------------
__global__ void deg_kernel(const int* __restrict__ dst) {
    int e = blockIdx.x * blockDim.x + threadIdx.x;
    if (e < EE) redI1(&g_deg[__ldg(&dst[e])], 1);
}

// scan1 also accumulates per-graph node counts (runs AFTER init zeroed g_cnt)
__global__ __launch_bounds__(SCAN_B) void scan1_kernel(const int* __restrict__ graph_id) {
    __shared__ int sh[SCAN_B];
    __shared__ int cnt[GG];
    int t = threadIdx.x;
    int i = blockIdx.x * SCAN_B + t;
    if (t < GG) cnt[t] = 0;
    sh[t] = (i < NN) ? g_deg[i] : 0;
    __syncthreads();
    if (i < NN) atomicAdd(&cnt[__ldg(&graph_id[i])], 1);
#pragma unroll
    for (int s = SCAN_B / 2; s > 0; s >>= 1) {
        if (t < s) sh[t] += sh[t + s];
        __syncthreads();
    }
    if (t == 0) g_bsum[blockIdx.x] = sh[0];
    if (t < GG && cnt[t]) redI1(&g_cnt[t], cnt[t]);
}

// scan3 computes its own block offset from g_bsum (scan2 deleted)
__global__ __launch_bounds__(SCAN_B) void scan3_kernel() {
    __shared__ int sh[SCAN_B];
    __shared__ int offs[128];
    int t = threadIdx.x;
    int i = blockIdx.x * SCAN_B + t;
    if (t < 128)
        offs[t] = (t < blockIdx.x && t < SCAN_NBLK) ? g_bsum[t] : 0;
    int v = (i < NN) ? g_deg[i] : 0;
    sh[t] = v;
    __syncthreads();
#pragma unroll
    for (int s = 64; s > 0; s >>= 1) {
        if (t < s) offs[t] += offs[t + s];
        __syncthreads();
    }
    int boff = offs[0];
#pragma unroll
    for (int off = 1; off < SCAN_B; off <<= 1) {
        int x = (t >= off) ? sh[t - off] : 0;
        __syncthreads();
        sh[t] += x;
        __syncthreads();
    }
    if (i < NN) {
        int pos = boff + sh[t] - v;     // exclusive
        g_ptr[i] = pos;
        g_cur[i] = pos;
    }
}

__global__ void fill_kernel(const int* __restrict__ src,
                            const int* __restrict__ dst) {
    int e = blockIdx.x * blockDim.x + threadIdx.x;
    if (e >= EE) return;
    int d = __ldg(&dst[e]);
    int pos = atomicAdd(&g_cur[d], 1);
    g_esrc[pos] = __ldg(&src[e]);
}

// ---------------- K1: gather-aggregate (warp per node, uniform esrc load) -------
__global__ __launch_bounds__(256) void agg_kernel() {
    int t = blockIdx.x * blockDim.x + threadIdx.x;
    int node = t >> 5;
    if (node >= NN) return;
    int lane = t & 31;
    int beg = __ldg(&g_ptr[node]);
    int d = __ldg(&g_deg[node]);
    float2 a0 = make_float2(0.f, 0.f), a1 = make_float2(0.f, 0.f);
    const uint2* base = (const uint2*)g_feath;   // 32 uint2 per row
    for (int i = 0; i < d; i++) {
        int s = __ldg(&g_esrc[beg + i]);
        uint2 u = __ldg(base + (size_t)s * 32 + lane);
        float2 f0 = __half22float2(*(__half2*)&u.x);
        float2 f1 = __half22float2(*(__half2*)&u.y);
        a0.x += f0.x; a0.y += f0.y; a1.x += f1.x; a1.y += f1.y;
    }
    float sc = 1.f / fmaxf((float)d, 1.f);       // feath already has the 1/32
    __half h0 = __float2half(a0.x * sc);
    __half h1 = __float2half(a0.y * sc);
    __half h2 = __float2half(a1.x * sc);
    __half h3 = __float2half(a1.y * sc);
    uint2 o;
    o.x = ((uint32_t)__half_as_ushort(h1) << 16) | __half_as_ushort(h0);
    o.y = ((uint32_t)__half_as_ushort(h3) << 16) | __half_as_ushort(h2);
    ((uint2*)g_aggh)[(size_t)node * 32 + lane] = o;
}

// ---------------- K2: mma.sync fp16 GEMM, 3-stage cp.async pipeline -------------
// stage ring: 3 x ST_SZ (A [128][80B] + W [32][528B]) = 81408 bytes.
// Epilogue aliases ring smem after the mainloop barrier.
#define ST_SZ    27136
#define SOF_WH   10240
#define OFF_CS   67584
#define OFF_CQ   71680
#define OFF_POOL 75776
#define OFF_BSH  88064
#define OFF_GIDS 89088
#define OFF_GRNG 89600
#define DYN_SMEM 89616

__global__ __launch_bounds__(1024, 1) void conv_mma_kernel(
    const float* __restrict__ b_conv, const int* __restrict__ graph_id) {
    extern __shared__ char p0[];
    uint32_t sm = smem_u32(p0);
    float* s_bsh  = (float*)(p0 + OFF_BSH);
    int*   s_gids = (int*)(p0 + OFF_GIDS);
    int*   s_grng = (int*)(p0 + OFF_GRNG);

    int tid = threadIdx.x;
    int wid = tid >> 5;
    int lane = tid & 31;
    int row0 = blockIdx.x * TILE_M;

    if (tid < 256) s_bsh[tid] = b_conv[tid];
    if (tid < TILE_M) {
        int node = row0 + tid;
        s_gids[tid] = (node < NN) ? __ldg(&graph_id[node]) : -1;
    }
    __syncthreads();
    if (tid == 0) {
        int lo = s_gids[0], hi = lo;
#pragma unroll 1
        for (int i = 1; i < TILE_M; i++)
            if (s_gids[i] >= 0) hi = s_gids[i];
        s_grng[0] = lo; s_grng[1] = hi;
    }

    int wm = (wid >> 2) * 16;    // warp M offset (0..112)
    int wn = (wid & 3) * 64;     // warp N offset (0/64/128/192)

    float acc[8][4];
#pragma unroll
    for (int j = 0; j < 8; j++)
#pragma unroll
        for (int d = 0; d < 4; d++) acc[j][d] = 0.f;

    uint32_t Abase = sm + (wm + (lane & 15)) * 80 + (lane >> 4) * 16;
    uint32_t Bbase = sm + SOF_WH + (lane & 15) * 528 + (wn + (lane >> 4) * 8) * 2;

    auto stage = [&](int kc, int buf) {
        uint32_t st = sm + buf * ST_SZ;
        {
            int r = tid >> 3, u = tid & 7;
            const __half* srcb = (kc < 4) ? g_feath : g_aggh;
            int kof = (kc & 3) * 32;
            cpa8(st + r * 80 + u * 8,
                 srcb + (size_t)(row0 + r) * IND + kof + u * 4);
        }
        {
            int kk = tid >> 5, c = tid & 31;
            size_t so = (size_t)(kc * 32 + kk) * 256 + c * 8;
            cpa16(st + SOF_WH + kk * 528 + c * 16, g_Whi + so);
        }
    };
    auto compute = [&](int buf) {
        uint32_t so = buf * ST_SZ;
#pragma unroll
        for (int ks = 0; ks < 2; ks++) {
            uint32_t ab = Abase + so + ks * 32;
            uint32_t bb = Bbase + so + ks * 8448;   // ks*16*528
            uint32_t ah[4], f[4];
            ldsm4(ah, ab);
#pragma unroll
            for (int c = 0; c < 4; c++) {
                ldsm4t(f, bb + c * 32);
                mma16816(acc[2 * c], ah, f);
                mma16816(acc[2 * c + 1], ah, f + 2);
            }
        }
    };

    // -------- main loop: 8 K-chunks, 3-stage cp.async ring --------
    stage(0, 0); CP_COMMIT();
    stage(1, 1); CP_COMMIT();
#pragma unroll 1
    for (int kc = 0; kc < 8; kc++) {
        if (kc < 7) CP_WAIT1(); else CP_WAIT0();   // stage kc complete
        __syncthreads();                            // visible to all warps
        compute(kc % 3);
        if (kc < 6) { stage(kc + 2, (kc + 2) % 3); CP_COMMIT(); }
    }
    __syncthreads();   // all reads of ring smem done before epilogue aliases it

    // -------- epilogue --------
    __half* C  = (__half*)p0;                 // [128][264]
    float* s_cs = (float*)(p0 + OFF_CS);      // [4][256]
    float* s_cq = (float*)(p0 + OFF_CQ);      // [4][256]
    float* s_pl = (float*)(p0 + OFF_POOL);    // [8][256]
#pragma unroll
    for (int j = 0; j < 8; j++) {
        int r0 = wm + (lane >> 2);
        int c = wn + j * 8 + (lane & 3) * 2;
        __half2 lo2 = __floats2half2_rn(acc[j][0], acc[j][1]);
        __half2 hi2 = __floats2half2_rn(acc[j][2], acc[j][3]);
        *(__half2*)&C[r0 * 264 + c] = lo2;
        *(__half2*)&C[(r0 + 8) * 264 + c] = hi2;
    }
    __syncthreads();
    ((float*)s_pl)[tid] = 0.f;
    ((float*)s_pl)[tid + 1024] = 0.f;
    __syncthreads();

    int col = tid & 255, q = tid >> 8;
    int glo = s_grng[0], ghi = s_grng[1];
    {
        float b = s_bsh[col];
        float sum = 0.f, sq = 0.f;
        int curg = -1;
        float run = 0.f;
#pragma unroll 4
        for (int rr = q * 32; rr < q * 32 + 32; rr++) {
            int gd = s_gids[rr];
            float v = __half2float(C[rr * 264 + col]) + b;
            v = (gd >= 0) ? fmaxf(v, 0.f) : 0.f;
            C[rr * 264 + col] = __float2half(v);
            sum += v; sq += v * v;
            if (gd != curg) {
                int slot = curg - glo;
                if (curg >= 0 && slot < 8) atomicAdd(&s_pl[slot * 256 + col], run);
                run = 0.f; curg = gd;
            }
            run += v;
        }
        int slot = curg - glo;
        if (curg >= 0 && slot < 8) atomicAdd(&s_pl[slot * 256 + col], run);
        s_cs[q * 256 + col] = sum;
        s_cq[q * 256 + col] = sq;
    }
    __syncthreads();
    if (tid < 256) {
        float s = s_cs[col] + s_cs[256 + col] + s_cs[512 + col] + s_cs[768 + col];
        redF1(&g_bnstats[col], s);
#pragma unroll 1
        for (int t = 0; t < 8; t++) {
            int g = glo + t;
            if (g <= ghi) redF1(&g_poolraw[g * HID + col], s_pl[t * 256 + col]);
        }
    } else if (tid < 512) {
        int c2 = tid - 256;
        float s = s_cq[c2] + s_cq[256 + c2] + s_cq[512 + c2] + s_cq[768 + c2];
        redF1(&g_bnstats[256 + c2], s);
    }
#pragma unroll 1
    for (int p = 1; glo + 8 * p <= ghi; p++) {
        __syncthreads();
        ((float*)s_pl)[tid] = 0.f;
        ((float*)s_pl)[tid + 1024] = 0.f;
        __syncthreads();
        int base = glo + 8 * p;
        int curg = -1;
        float run = 0.f;
#pragma unroll 1
        for (int rr = q * 32; rr < q * 32 + 32; rr++) {
            int gd = s_gids[rr];
            float v = __half2float(C[rr * 264 + col]);
            if (gd != curg) {
                int slot = curg - base;
                if (slot >= 0 && slot < 8) atomicAdd(&s_pl[slot * 256 + col], run);
                run = 0.f; curg = gd;
            }
            run += v;
        }
        int slot = curg - base;
        if (slot >= 0 && slot < 8) atomicAdd(&s_pl[slot * 256 + col], run);
        __syncthreads();
        if (tid < 256) {
#pragma unroll 1
            for (int t = 0; t < 8; t++) {
                int g = base + t;
                if (g <= ghi) redF1(&g_poolraw[g * HID + col], s_pl[t * 256 + col]);
            }
        }
    }
}

// ---------------- K4: merged head — lp1+lp2+lp3 with software grid barriers ------
__global__ __launch_bounds__(HID) void head_kernel(
    const float* __restrict__ W_lp, const float* __restrict__ b_lp,
    const float* __restrict__ gamma_c, const float* __restrict__ beta_c,
    const float* __restrict__ gamma_lp, const float* __restrict__ beta_lp,
    float* __restrict__ out_p, float* __restrict__ out) {
    __shared__ float row[HID];
    int g = blockIdx.x, c = threadIdx.x;

    // phase 1: pooled (BN-conv folded) -> z1 = relu(pooled @ W + b), stats
    float mean = g_bnstats[c] * (1.0f / NN);
    float var  = g_bnstats[256 + c] * (1.0f / NN) - mean * mean;
    float sc = gamma_c[c] * rsqrtf(var + BN_EPS);
    float sh = beta_c[c] - mean * sc;
    float cntf = (float)g_cnt[g];
    row[c] = fmaf(g_poolraw[g * HID + c], sc, cntf * sh);
    __syncthreads();
    float acc = b_lp[c];
#pragma unroll 8
    for (int k = 0; k < HID; k++) acc = fmaf(row[k], __ldg(&W_lp[k * HID + c]), acc);
    float r = fmaxf(acc, 0.f);
    redF1(&g_bnstats[512 + c], r);
    redF1(&g_bnstats[768 + c], r * r);
    __threadfence();
    __syncthreads();
    if (c == 0) {
        atomicAdd(&g_bar1, 1);
        while (atomicAdd(&g_bar1, 0) < GG) { }
    }
    __syncthreads();

    // phase 2: p = BN(z1), out_p; z2 = relu(p @ W + b), stats
    float m1 = __ldcg(&g_bnstats[512 + c]) * (1.f / GG);
    float v1 = __ldcg(&g_bnstats[768 + c]) * (1.f / GG) - m1 * m1;
    float p = (r - m1) * rsqrtf(v1 + BN_EPS) * gamma_lp[c] + beta_lp[c];
    out_p[g * HID + c] = p;
    row[c] = p;
    __syncthreads();
    acc = b_lp[c];
#pragma unroll 8
    for (int k = 0; k < HID; k++) acc = fmaf(row[k], __ldg(&W_lp[k * HID + c]), acc);
    float r2 = fmaxf(acc, 0.f);
    redF1(&g_bnstats[1024 + c], r2);
    redF1(&g_bnstats[1280 + c], r2 * r2);
    __threadfence();
    __syncthreads();
    if (c == 0) {
        atomicAdd(&g_bar2, 1);
        while (atomicAdd(&g_bar2, 0) < GG) { }
    }
    __syncthreads();

    // phase 3: BN(z2) + log_softmax
    float m2 = __ldcg(&g_bnstats[1024 + c]) * (1.f / GG);
    float v2 = __ldcg(&g_bnstats[1280 + c]) * (1.f / GG) - m2 * m2;
    float o = (r2 - m2) * rsqrtf(v2 + BN_EPS) * gamma_lp[c] + beta_lp[c];
    row[c] = o;
    __syncthreads();
    for (int s = 128; s > 0; s >>= 1) {
        if (c < s) row[c] = fmaxf(row[c], row[c + s]);
        __syncthreads();
    }
    float mx = row[0];
    __syncthreads();
    float e = expf(o - mx);
    row[c] = e;
    __syncthreads();
    for (int s = 128; s > 0; s >>= 1) {
        if (c < s) row[c] += row[c + s];
        __syncthreads();
    }
    float lse = logf(row[0]);
    out[g * HID + c] = o - mx - lse;
}

// ---------------- launch ----------------
extern "C" void kernel_launch(void* const* d_in, const int* in_sizes, int n_in,
                              void* d_out, int out_size) {
    const float* feat       = (const float*)d_in[0];
    const float* W_self     = (const float*)d_in[1];
    const float* W_neigh    = (const float*)d_in[2];
    const float* b_conv     = (const float*)d_in[3];
    const float* gamma_conv = (const float*)d_in[4];
    const float* beta_conv  = (const float*)d_in[5];
    const float* W_lp       = (const float*)d_in[6];
    const float* b_lp       = (const float*)d_in[7];
    const float* gamma_lp   = (const float*)d_in[8];
    const float* beta_lp    = (const float*)d_in[9];
    const int*   src        = (const int*)d_in[10];
    const int*   dst        = (const int*)d_in[11];
    const int*   graph_id   = (const int*)d_in[12];
    float* out = (float*)d_out;

    float* out_p;
    if (out_size >= 2 * GG * HID) {
        out_p = out + GG * HID;
    } else {
        void* pp = nullptr;
        cudaGetSymbolAddress(&pp, g_p);
        out_p = (float*)pp;
    }

    cudaFuncSetAttribute(conv_mma_kernel,
                         cudaFuncAttributeMaxDynamicSharedMemorySize, DYN_SMEM);

    init_kernel<<<(NN * (IND / 4) + 255) / 256, 256>>>(feat, W_self, W_neigh);
    deg_kernel<<<(EE + 255) / 256, 256>>>(dst);
    scan1_kernel<<<SCAN_NBLK, SCAN_B>>>(graph_id);
    scan3_kernel<<<SCAN_NBLK, SCAN_B>>>();
    fill_kernel<<<(EE + 255) / 256, 256>>>(src, dst);
    agg_kernel<<<(NN * 32 + 255) / 256, 256>>>();
    conv_mma_kernel<<<MBLK, 1024, DYN_SMEM>>>(b_conv, graph_id);
    head_kernel<<<GG, HID>>>(W_lp, b_lp, gamma_conv, beta_conv,
                             gamma_lp, beta_lp, out_p, out);
}

// round 17
// speedup vs baseline: 1.4843x; 1.0103x over previous
#include <cuda_runtime.h>
#include <cuda_fp16.h>
#include <cstdint>

#define NN  100000
#define EE  1000000
#define IND 128
#define HID 256
#define GG  64
#define BN_EPS 1e-5f

#define SCAN_B 1024
#define SCAN_NBLK ((NN + SCAN_B - 1) / SCAN_B)   // 98

#define TILE_M 128
#define MBLK ((NN + TILE_M - 1) / TILE_M)        // 782

#define WSCALE 32.0f
#define AINV   0.03125f

// ---------------- scratch (static device globals; statically zero at load) ------
// Invariant: g_deg, g_cnt, g_bnstats, g_poolraw, g_bar1/2 are ZERO at entry to
// every kernel_launch execution (static zero-init for the first; cleanup_kernel
// re-zeroes at the end of each execution). Pads of g_feath/g_aggh are never
// written non-zero by anyone, so they stay zero forever.
__device__ __half g_feath[(NN + TILE_M) * IND];  // feat * (1/32), fp16, padded
__device__ __half g_aggh[(NN + TILE_M) * IND];   // h_neigh * (1/32), fp16, padded
__device__ int   g_deg[NN];
__device__ int   g_ptr[NN];
__device__ int   g_cur[NN];
__device__ int   g_esrc[EE];
__device__ int   g_bsum[SCAN_NBLK];
__device__ float g_poolraw[GG * HID];
__device__ int   g_cnt[GG];
__device__ float g_bnstats[8 * HID];
__device__ float g_p[GG * HID];
__device__ int   g_bar1, g_bar2;
__device__ __half g_Whi[256 * 256];              // W * 32, fp16 (single term)

// ---------------- helpers ----------------
__device__ __forceinline__ void redF1(float* addr, float v) {
    asm volatile("red.global.add.f32 [%0], %1;" :: "l"(addr), "f"(v) : "memory");
}
__device__ __forceinline__ void redI1(int* addr, int v) {
    asm volatile("red.global.add.s32 [%0], %1;" :: "l"(addr), "r"(v) : "memory");
}
__device__ __forceinline__ uint32_t smem_u32(const void* p) {
    uint32_t a;
    asm("{ .reg .u64 t; cvta.to.shared.u64 t, %1; cvt.u32.u64 %0, t; }"
        : "=r"(a) : "l"(p));
    return a;
}
__device__ __forceinline__ void ldsm4(uint32_t* r, uint32_t a) {
    asm volatile("ldmatrix.sync.aligned.m8n8.x4.shared.b16 {%0,%1,%2,%3}, [%4];"
        : "=r"(r[0]), "=r"(r[1]), "=r"(r[2]), "=r"(r[3]) : "r"(a));
}
__device__ __forceinline__ void ldsm4t(uint32_t* r, uint32_t a) {
    asm volatile("ldmatrix.sync.aligned.m8n8.x4.trans.shared.b16 {%0,%1,%2,%3}, [%4];"
        : "=r"(r[0]), "=r"(r[1]), "=r"(r[2]), "=r"(r[3]) : "r"(a));
}
__device__ __forceinline__ void mma16816(float* d, const uint32_t* a, const uint32_t* b) {
    asm volatile("mma.sync.aligned.m16n8k16.row.col.f32.f16.f16.f32 "
        "{%0,%1,%2,%3}, {%4,%5,%6,%7}, {%8,%9}, {%0,%1,%2,%3};"
        : "+f"(d[0]), "+f"(d[1]), "+f"(d[2]), "+f"(d[3])
        : "r"(a[0]), "r"(a[1]), "r"(a[2]), "r"(a[3]), "r"(b[0]), "r"(b[1]));
}
__device__ __forceinline__ void cpa16(uint32_t d, const void* s) {
    asm volatile("cp.async.cg.shared.global [%0], [%1], 16;" :: "r"(d), "l"(s));
}
__device__ __forceinline__ void cpa8(uint32_t d, const void* s) {
    asm volatile("cp.async.ca.shared.global [%0], [%1], 8;" :: "r"(d), "l"(s));
}
#define CP_COMMIT() asm volatile("cp.async.commit_group;" ::: "memory")
#define CP_WAIT0()  asm volatile("cp.async.wait_group 0;" ::: "memory")
#define CP_WAIT1()  asm volatile("cp.async.wait_group 1;" ::: "memory")

// ---------------- K0: init — feat->fp16 image + W prep + degree atomics ---------
// g_deg is zero at entry (static zero / cleanup); degree atomics overlap the
// memory-bound feat sweep.
__global__ void init_kernel(const float* __restrict__ feat,
                            const float* __restrict__ W_self,
                            const float* __restrict__ W_neigh,
                            const int* __restrict__ dst) {
    int idx = blockIdx.x * blockDim.x + threadIdx.x;
    if (idx < NN * (IND / 4)) {
        float4 v = __ldg(((const float4*)feat) + idx);
        __half h0 = __float2half(v.x * AINV);
        __half h1 = __float2half(v.y * AINV);
        __half h2 = __float2half(v.z * AINV);
        __half h3 = __float2half(v.w * AINV);
        uint2 u;
        u.x = ((uint32_t)__half_as_ushort(h1) << 16) | __half_as_ushort(h0);
        u.y = ((uint32_t)__half_as_ushort(h3) << 16) | __half_as_ushort(h2);
        ((uint2*)g_feath)[idx] = u;
    }
    if (idx < 65536) {
        int k = idx >> 8, n = idx & 255;
        float w = ((k < IND) ? W_self[k * HID + n] : W_neigh[(k - IND) * HID + n]) * WSCALE;
        g_Whi[idx] = __float2half(w);
    }
    if (idx < EE) redI1(&g_deg[__ldg(&dst[idx])], 1);
}

// scan1 also accumulates per-graph node counts (g_cnt zero at entry)
__global__ __launch_bounds__(SCAN_B) void scan1_kernel(const int* __restrict__ graph_id) {
    __shared__ int sh[SCAN_B];
    __shared__ int cnt[GG];
    int t = threadIdx.x;
    int i = blockIdx.x * SCAN_B + t;
    if (t < GG) cnt[t] = 0;
    sh[t] = (i < NN) ? g_deg[i] : 0;
    __syncthreads();
    if (i < NN) atomicAdd(&cnt[__ldg(&graph_id[i])], 1);
#pragma unroll
    for (int s = SCAN_B / 2; s > 0; s >>= 1) {
        if (t < s) sh[t] += sh[t + s];
        __syncthreads();
    }
    if (t == 0) g_bsum[blockIdx.x] = sh[0];
    if (t < GG && cnt[t]) redI1(&g_cnt[t], cnt[t]);
}

// scan3 computes its own block offset from g_bsum
__global__ __launch_bounds__(SCAN_B) void scan3_kernel() {
    __shared__ int sh[SCAN_B];
    __shared__ int offs[128];
    int t = threadIdx.x;
    int i = blockIdx.x * SCAN_B + t;
    if (t < 128)
        offs[t] = (t < blockIdx.x && t < SCAN_NBLK) ? g_bsum[t] : 0;
    int v = (i < NN) ? g_deg[i] : 0;
    sh[t] = v;
    __syncthreads();
#pragma unroll
    for (int s = 64; s > 0; s >>= 1) {
        if (t < s) offs[t] += offs[t + s];
        __syncthreads();
    }
    int boff = offs[0];
#pragma unroll
    for (int off = 1; off < SCAN_B; off <<= 1) {
        int x = (t >= off) ? sh[t - off] : 0;
        __syncthreads();
        sh[t] += x;
        __syncthreads();
    }
    if (i < NN) {
        int pos = boff + sh[t] - v;     // exclusive
        g_ptr[i] = pos;
        g_cur[i] = pos;
    }
}

// fill: 4 edges per thread (int4)
__global__ void fill_kernel(const int4* __restrict__ src4,
                            const int4* __restrict__ dst4) {
    int e4 = blockIdx.x * blockDim.x + threadIdx.x;
    if (e4 >= EE / 4) return;
    int4 d = __ldg(&dst4[e4]);
    int4 s = __ldg(&src4[e4]);
    g_esrc[atomicAdd(&g_cur[d.x], 1)] = s.x;
    g_esrc[atomicAdd(&g_cur[d.y], 1)] = s.y;
    g_esrc[atomicAdd(&g_cur[d.z], 1)] = s.z;
    g_esrc[atomicAdd(&g_cur[d.w], 1)] = s.w;
}

// ---------------- K1: gather-aggregate (warp per node, uniform esrc load) -------
__global__ __launch_bounds__(256) void agg_kernel() {
    int t = blockIdx.x * blockDim.x + threadIdx.x;
    int node = t >> 5;
    if (node >= NN) return;
    int lane = t & 31;
    int beg = __ldg(&g_ptr[node]);
    int d = __ldg(&g_deg[node]);
    float2 a0 = make_float2(0.f, 0.f), a1 = make_float2(0.f, 0.f);
    const uint2* base = (const uint2*)g_feath;   // 32 uint2 per row
    for (int i = 0; i < d; i++) {
        int s = __ldg(&g_esrc[beg + i]);
        uint2 u = __ldg(base + (size_t)s * 32 + lane);
        float2 f0 = __half22float2(*(__half2*)&u.x);
        float2 f1 = __half22float2(*(__half2*)&u.y);
        a0.x += f0.x; a0.y += f0.y; a1.x += f1.x; a1.y += f1.y;
    }
    float sc = 1.f / fmaxf((float)d, 1.f);       // feath already has the 1/32
    __half h0 = __float2half(a0.x * sc);
    __half h1 = __float2half(a0.y * sc);
    __half h2 = __float2half(a1.x * sc);
    __half h3 = __float2half(a1.y * sc);
    uint2 o;
    o.x = ((uint32_t)__half_as_ushort(h1) << 16) | __half_as_ushort(h0);
    o.y = ((uint32_t)__half_as_ushort(h3) << 16) | __half_as_ushort(h2);
    ((uint2*)g_aggh)[(size_t)node * 32 + lane] = o;
}

// ---------------- K2: mma.sync fp16 GEMM, 3-stage cp.async pipeline -------------
#define ST_SZ    27136
#define SOF_WH   10240
#define OFF_CS   67584
#define OFF_CQ   71680
#define OFF_POOL 75776
#define OFF_BSH  88064
#define OFF_GIDS 89088
#define OFF_GRNG 89600
#define DYN_SMEM 89616

__global__ __launch_bounds__(1024, 1) void conv_mma_kernel(
    const float* __restrict__ b_conv, const int* __restrict__ graph_id) {
    extern __shared__ char p0[];
    uint32_t sm = smem_u32(p0);
    float* s_bsh  = (float*)(p0 + OFF_BSH);
    int*   s_gids = (int*)(p0 + OFF_GIDS);
    int*   s_grng = (int*)(p0 + OFF_GRNG);

    int tid = threadIdx.x;
    int wid = tid >> 5;
    int lane = tid & 31;
    int row0 = blockIdx.x * TILE_M;

    if (tid < 256) s_bsh[tid] = b_conv[tid];
    if (tid < TILE_M) {
        int node = row0 + tid;
        s_gids[tid] = (node < NN) ? __ldg(&graph_id[node]) : -1;
    }
    __syncthreads();
    if (tid == 0) {
        int lo = s_gids[0], hi = lo;
#pragma unroll 1
        for (int i = 1; i < TILE_M; i++)
            if (s_gids[i] >= 0) hi = s_gids[i];
        s_grng[0] = lo; s_grng[1] = hi;
    }

    int wm = (wid >> 2) * 16;    // warp M offset (0..112)
    int wn = (wid & 3) * 64;     // warp N offset (0/64/128/192)

    float acc[8][4];
#pragma unroll
    for (int j = 0; j < 8; j++)
#pragma unroll
        for (int d = 0; d < 4; d++) acc[j][d] = 0.f;

    uint32_t Abase = sm + (wm + (lane & 15)) * 80 + (lane >> 4) * 16;
    uint32_t Bbase = sm + SOF_WH + (lane & 15) * 528 + (wn + (lane >> 4) * 8) * 2;

    auto stage = [&](int kc, int buf) {
        uint32_t st = sm + buf * ST_SZ;
        {
            int r = tid >> 3, u = tid & 7;
            const __half* srcb = (kc < 4) ? g_feath : g_aggh;
            int kof = (kc & 3) * 32;
            cpa8(st + r * 80 + u * 8,
                 srcb + (size_t)(row0 + r) * IND + kof + u * 4);
        }
        {
            int kk = tid >> 5, c = tid & 31;
            size_t so = (size_t)(kc * 32 + kk) * 256 + c * 8;
            cpa16(st + SOF_WH + kk * 528 + c * 16, g_Whi + so);
        }
    };
    auto compute = [&](int buf) {
        uint32_t so = buf * ST_SZ;
#pragma unroll
        for (int ks = 0; ks < 2; ks++) {
            uint32_t ab = Abase + so + ks * 32;
            uint32_t bb = Bbase + so + ks * 8448;   // ks*16*528
            uint32_t ah[4], f[4];
            ldsm4(ah, ab);
#pragma unroll
            for (int c = 0; c < 4; c++) {
                ldsm4t(f, bb + c * 32);
                mma16816(acc[2 * c], ah, f);
                mma16816(acc[2 * c + 1], ah, f + 2);
            }
        }
    };

    // -------- main loop: 8 K-chunks, 3-stage cp.async ring --------
    stage(0, 0); CP_COMMIT();
    stage(1, 1); CP_COMMIT();
#pragma unroll 1
    for (int kc = 0; kc < 8; kc++) {
        if (kc < 7) CP_WAIT1(); else CP_WAIT0();
        __syncthreads();
        compute(kc % 3);
        if (kc < 6) { stage(kc + 2, (kc + 2) % 3); CP_COMMIT(); }
    }
    __syncthreads();

    // -------- epilogue --------
    __half* C  = (__half*)p0;                 // [128][264]
    float* s_cs = (float*)(p0 + OFF_CS);
    float* s_cq = (float*)(p0 + OFF_CQ);
    float* s_pl = (float*)(p0 + OFF_POOL);
#pragma unroll
    for (int j = 0; j < 8; j++) {
        int r0 = wm + (lane >> 2);
        int c = wn + j * 8 + (lane & 3) * 2;
        __half2 lo2 = __floats2half2_rn(acc[j][0], acc[j][1]);
        __half2 hi2 = __floats2half2_rn(acc[j][2], acc[j][3]);
        *(__half2*)&C[r0 * 264 + c] = lo2;
        *(__half2*)&C[(r0 + 8) * 264 + c] = hi2;
    }
    __syncthreads();
    ((float*)s_pl)[tid] = 0.f;
    ((float*)s_pl)[tid + 1024] = 0.f;
    __syncthreads();

    int col = tid & 255, q = tid >> 8;
    int glo = s_grng[0], ghi = s_grng[1];
    {
        float b = s_bsh[col];
        float sum = 0.f, sq = 0.f;
        int curg = -1;
        float run = 0.f;
#pragma unroll 4
        for (int rr = q * 32; rr < q * 32 + 32; rr++) {
            int gd = s_gids[rr];
            float v = __half2float(C[rr * 264 + col]) + b;
            v = (gd >= 0) ? fmaxf(v, 0.f) : 0.f;
            C[rr * 264 + col] = __float2half(v);
            sum += v; sq += v * v;
            if (gd != curg) {
                int slot = curg - glo;
                if (curg >= 0 && slot < 8) atomicAdd(&s_pl[slot * 256 + col], run);
                run = 0.f; curg = gd;
            }
            run += v;
        }
        int slot = curg - glo;
        if (curg >= 0 && slot < 8) atomicAdd(&s_pl[slot * 256 + col], run);
        s_cs[q * 256 + col] = sum;
        s_cq[q * 256 + col] = sq;
    }
    __syncthreads();
    if (tid < 256) {
        float s = s_cs[col] + s_cs[256 + col] + s_cs[512 + col] + s_cs[768 + col];
        redF1(&g_bnstats[col], s);
#pragma unroll 1
        for (int t = 0; t < 8; t++) {
            int g = glo + t;
            if (g <= ghi) redF1(&g_poolraw[g * HID + col], s_pl[t * 256 + col]);
        }
    } else if (tid < 512) {
        int c2 = tid - 256;
        float s = s_cq[c2] + s_cq[256 + c2] + s_cq[512 + c2] + s_cq[768 + c2];
        redF1(&g_bnstats[256 + c2], s);
    }
#pragma unroll 1
    for (int p = 1; glo + 8 * p <= ghi; p++) {
        __syncthreads();
        ((float*)s_pl)[tid] = 0.f;
        ((float*)s_pl)[tid + 1024] = 0.f;
        __syncthreads();
        int base = glo + 8 * p;
        int curg = -1;
        float run = 0.f;
#pragma unroll 1
        for (int rr = q * 32; rr < q * 32 + 32; rr++) {
            int gd = s_gids[rr];
            float v = __half2float(C[rr * 264 + col]);
            if (gd != curg) {
                int slot = curg - base;
                if (slot >= 0 && slot < 8) atomicAdd(&s_pl[slot * 256 + col], run);
                run = 0.f; curg = gd;
            }
            run += v;
        }
        int slot = curg - base;
        if (slot >= 0 && slot < 8) atomicAdd(&s_pl[slot * 256 + col], run);
        __syncthreads();
        if (tid < 256) {
#pragma unroll 1
            for (int t = 0; t < 8; t++) {
                int g = base + t;
                if (g <= ghi) redF1(&g_poolraw[g * HID + col], s_pl[t * 256 + col]);
            }
        }
    }
}

// ---------------- K4: merged head — lp1+lp2+lp3 with software grid barriers ------
__global__ __launch_bounds__(HID) void head_kernel(
    const float* __restrict__ W_lp, const float* __restrict__ b_lp,
    const float* __restrict__ gamma_c, const float* __restrict__ beta_c,
    const float* __restrict__ gamma_lp, const float* __restrict__ beta_lp,
    float* __restrict__ out_p, float* __restrict__ out) {
    __shared__ float row[HID];
    int g = blockIdx.x, c = threadIdx.x;

    float mean = g_bnstats[c] * (1.0f / NN);
    float var  = g_bnstats[256 + c] * (1.0f / NN) - mean * mean;
    float sc = gamma_c[c] * rsqrtf(var + BN_EPS);
    float sh = beta_c[c] - mean * sc;
    float cntf = (float)g_cnt[g];
    row[c] = fmaf(g_poolraw[g * HID + c], sc, cntf * sh);
    __syncthreads();
    float acc = b_lp[c];
#pragma unroll 8
    for (int k = 0; k < HID; k++) acc = fmaf(row[k], __ldg(&W_lp[k * HID + c]), acc);
    float r = fmaxf(acc, 0.f);
    redF1(&g_bnstats[512 + c], r);
    redF1(&g_bnstats[768 + c], r * r);
    __threadfence();
    __syncthreads();
    if (c == 0) {
        atomicAdd(&g_bar1, 1);
        while (atomicAdd(&g_bar1, 0) < GG) { }
    }
    __syncthreads();

    float m1 = __ldcg(&g_bnstats[512 + c]) * (1.f / GG);
    float v1 = __ldcg(&g_bnstats[768 + c]) * (1.f / GG) - m1 * m1;
    float p = (r - m1) * rsqrtf(v1 + BN_EPS) * gamma_lp[c] + beta_lp[c];
    out_p[g * HID + c] = p;
    row[c] = p;
    __syncthreads();
    acc = b_lp[c];
#pragma unroll 8
    for (int k = 0; k < HID; k++) acc = fmaf(row[k], __ldg(&W_lp[k * HID + c]), acc);
    float r2 = fmaxf(acc, 0.f);
    redF1(&g_bnstats[1024 + c], r2);
    redF1(&g_bnstats[1280 + c], r2 * r2);
    __threadfence();
    __syncthreads();
    if (c == 0) {
        atomicAdd(&g_bar2, 1);
        while (atomicAdd(&g_bar2, 0) < GG) { }
    }
    __syncthreads();

    float m2 = __ldcg(&g_bnstats[1024 + c]) * (1.f / GG);
    float v2 = __ldcg(&g_bnstats[1280 + c]) * (1.f / GG) - m2 * m2;
    float o = (r2 - m2) * rsqrtf(v2 + BN_EPS) * gamma_lp[c] + beta_lp[c];
    row[c] = o;
    __syncthreads();
    for (int s = 128; s > 0; s >>= 1) {
        if (c < s) row[c] = fmaxf(row[c], row[c + s]);
        __syncthreads();
    }
    float mx = row[0];
    __syncthreads();
    float e = expf(o - mx);
    row[c] = e;
    __syncthreads();
    for (int s = 128; s > 0; s >>= 1) {
        if (c < s) row[c] += row[c + s];
        __syncthreads();
    }
    float lse = logf(row[0]);
    out[g * HID + c] = o - mx - lse;
}

// ---------------- K5: cleanup — restore the zero-state invariant ----------------
__global__ __launch_bounds__(256) void cleanup_kernel() {
    int idx = blockIdx.x * blockDim.x + threadIdx.x;   // 128*256 = 32768
#pragma unroll 1
    for (int i = idx; i < NN; i += 32768) g_deg[i] = 0;
    if (idx < GG * HID) g_poolraw[idx] = 0.f;
    if (idx < 8 * HID) g_bnstats[idx] = 0.f;
    if (idx < GG) g_cnt[idx] = 0;
    if (idx == 0) { g_bar1 = 0; g_bar2 = 0; }
}

// ---------------- launch ----------------
extern "C" void kernel_launch(void* const* d_in, const int* in_sizes, int n_in,
                              void* d_out, int out_size) {
    const float* feat       = (const float*)d_in[0];
    const float* W_self     = (const float*)d_in[1];
    const float* W_neigh    = (const float*)d_in[2];
    const float* b_conv     = (const float*)d_in[3];
    const float* gamma_conv = (const float*)d_in[4];
    const float* beta_conv  = (const float*)d_in[5];
    const float* W_lp       = (const float*)d_in[6];
    const float* b_lp       = (const float*)d_in[7];
    const float* gamma_lp   = (const float*)d_in[8];
    const float* beta_lp    = (const float*)d_in[9];
    const int*   src        = (const int*)d_in[10];
    const int*   dst        = (const int*)d_in[11];
    const int*   graph_id   = (const int*)d_in[12];
    float* out = (float*)d_out;

    float* out_p;
    if (out_size >= 2 * GG * HID) {
        out_p = out + GG * HID;
    } else {
        void* pp = nullptr;
        cudaGetSymbolAddress(&pp, g_p);
        out_p = (float*)pp;
    }

    cudaFuncSetAttribute(conv_mma_kernel,
                         cudaFuncAttributeMaxDynamicSharedMemorySize, DYN_SMEM);

    init_kernel<<<(NN * (IND / 4) + 255) / 256, 256>>>(feat, W_self, W_neigh, dst);
    scan1_kernel<<<SCAN_NBLK, SCAN_B>>>(graph_id);
    scan3_kernel<<<SCAN_NBLK, SCAN_B>>>();
    fill_kernel<<<(EE / 4 + 255) / 256, 256>>>((const int4*)src, (const int4*)dst);
    agg_kernel<<<(NN * 32 + 255) / 256, 256>>>();
    conv_mma_kernel<<<MBLK, 1024, DYN_SMEM>>>(b_conv, graph_id);
    head_kernel<<<GG, HID>>>(W_lp, b_lp, gamma_conv, beta_conv,
                             gamma_lp, beta_lp, out_p, out);
    cleanup_kernel<<<128, 256>>>();
}